// round 2
// baseline (speedup 1.0000x reference)
#include <cuda_runtime.h>
#include <math.h>

// Problem shape (fixed by the dataset)
#define Bb 16
#define Tt 2048
#define Ss 2048
#define Hh 1024
#define H2 2048

// GEMM tiling
#define BM 128
#define BN 128
#define BK 16

typedef unsigned long long ull;

// Scratch (device globals: no runtime allocation allowed)
__device__ __align__(16) float g_ctx[(size_t)Bb * Tt * Hh];
__device__ __align__(16) float g_attn_fallback[(size_t)Bb * Tt * Ss];

// ---------------------------------------------------------------------------
// Packed fp32x2 helpers (Blackwell sm_103a; ptxas never emits FFMA2 from C++)
// ---------------------------------------------------------------------------
__device__ __forceinline__ ull pack2(float x, float y) {
    ull r;
    asm("mov.b64 %0, {%1, %2};" : "=l"(r) : "f"(x), "f"(y));
    return r;
}
__device__ __forceinline__ float2 unpack2(ull u) {
    float2 f;
    asm("mov.b64 {%0, %1}, %2;" : "=f"(f.x), "=f"(f.y) : "l"(u));
    return f;
}
__device__ __forceinline__ void fma2(ull& d, ull a, ull b) {
    asm("fma.rn.f32x2 %0, %1, %2, %0;" : "+l"(d) : "l"(a), "l"(b));
}

// ---------------------------------------------------------------------------
// Generic batched GEMM: C[m,n] = sum_k A[m,k] * B(k,n)
//   TRANSB = 1: B stored [N,K] (k-major; C = A * B^T)  -- used for dec*enc^T
//   TRANSB = 0: B stored [K,N] (n-major)               -- used for P*enc
// All dims multiples of tile sizes -> no bounds checks.
// ---------------------------------------------------------------------------
template <int TRANSB>
__global__ void __launch_bounds__(256, 2) gemm_kernel(
    const float* __restrict__ A, const float* __restrict__ Bm,
    float* __restrict__ C,
    int K, int lda, int ldb, int ldc,
    size_t sA, size_t sB, size_t sC)
{
    __shared__ float As[BK][BM + 4];
    __shared__ float Bs[BK][BN + 4];

    A  += (size_t)blockIdx.z * sA;
    Bm += (size_t)blockIdx.z * sB;
    C  += (size_t)blockIdx.z * sC;

    const int tid = threadIdx.x;
    const int tx = tid & 15;
    const int ty = tid >> 4;
    const int m0 = blockIdx.y * BM;
    const int n0 = blockIdx.x * BN;

    ull acc[8][4];
#pragma unroll
    for (int i = 0; i < 8; i++)
#pragma unroll
        for (int j = 0; j < 4; j++) acc[i][j] = 0ull;

    for (int k0 = 0; k0 < K; k0 += BK) {
        // Stage A tile ([M,K] k-major) transposed into As[k][m]
#pragma unroll
        for (int i = 0; i < 2; i++) {
            int lin = tid + i * 256;
            int row = lin >> 2, c4 = lin & 3;
            float4 v = *(const float4*)(A + (size_t)(m0 + row) * lda + k0 + c4 * 4);
            As[c4 * 4 + 0][row] = v.x;
            As[c4 * 4 + 1][row] = v.y;
            As[c4 * 4 + 2][row] = v.z;
            As[c4 * 4 + 3][row] = v.w;
        }
        if (TRANSB) {
            // B is [N,K]: transpose-load into Bs[k][n]
#pragma unroll
            for (int i = 0; i < 2; i++) {
                int lin = tid + i * 256;
                int row = lin >> 2, c4 = lin & 3;
                float4 v = *(const float4*)(Bm + (size_t)(n0 + row) * ldb + k0 + c4 * 4);
                Bs[c4 * 4 + 0][row] = v.x;
                Bs[c4 * 4 + 1][row] = v.y;
                Bs[c4 * 4 + 2][row] = v.z;
                Bs[c4 * 4 + 3][row] = v.w;
            }
        } else {
            // B is [K,N]: direct copy
#pragma unroll
            for (int i = 0; i < 2; i++) {
                int lin = tid + i * 256;
                int kk = lin >> 5, n4 = lin & 31;
                float4 v = *(const float4*)(Bm + (size_t)(k0 + kk) * ldb + n0 + n4 * 4);
                *(float4*)&Bs[kk][n4 * 4] = v;
            }
        }
        __syncthreads();

#pragma unroll
        for (int kk = 0; kk < BK; kk++) {
            float4 a0 = *(const float4*)&As[kk][ty * 8];
            float4 a1 = *(const float4*)&As[kk][ty * 8 + 4];
            ulonglong2 b01 = *(const ulonglong2*)&Bs[kk][tx * 8];
            ulonglong2 b23 = *(const ulonglong2*)&Bs[kk][tx * 8 + 4];
            ull bv[4] = {b01.x, b01.y, b23.x, b23.y};
            ull av[8] = {pack2(a0.x, a0.x), pack2(a0.y, a0.y),
                         pack2(a0.z, a0.z), pack2(a0.w, a0.w),
                         pack2(a1.x, a1.x), pack2(a1.y, a1.y),
                         pack2(a1.z, a1.z), pack2(a1.w, a1.w)};
#pragma unroll
            for (int i = 0; i < 8; i++)
#pragma unroll
                for (int j = 0; j < 4; j++) fma2(acc[i][j], av[i], bv[j]);
        }
        __syncthreads();
    }

#pragma unroll
    for (int i = 0; i < 8; i++) {
        float* cp = C + (size_t)(m0 + ty * 8 + i) * ldc + n0 + tx * 8;
#pragma unroll
        for (int j = 0; j < 4; j++) *(ull*)(cp + 2 * j) = acc[i][j];
    }
}

// ---------------------------------------------------------------------------
// Row softmax over attn[b,t,:] (rows of length Ss=2048), in place.
// One block (256 thr) per row; each thread owns 8 contiguous elements.
// ---------------------------------------------------------------------------
__global__ void softmax_kernel(float* __restrict__ attn)
{
    __shared__ float red[8];
    float* p = attn + (size_t)blockIdx.x * Ss;
    const int tid = threadIdx.x;

    float4 v0 = *(const float4*)(p + tid * 8);
    float4 v1 = *(const float4*)(p + tid * 8 + 4);

    float m = fmaxf(fmaxf(fmaxf(v0.x, v0.y), fmaxf(v0.z, v0.w)),
                    fmaxf(fmaxf(v1.x, v1.y), fmaxf(v1.z, v1.w)));
#pragma unroll
    for (int o = 16; o > 0; o >>= 1) m = fmaxf(m, __shfl_xor_sync(0xffffffffu, m, o));
    if ((tid & 31) == 0) red[tid >> 5] = m;
    __syncthreads();
    float mm = red[0];
#pragma unroll
    for (int i = 1; i < 8; i++) mm = fmaxf(mm, red[i]);
    __syncthreads();

    v0.x = __expf(v0.x - mm); v0.y = __expf(v0.y - mm);
    v0.z = __expf(v0.z - mm); v0.w = __expf(v0.w - mm);
    v1.x = __expf(v1.x - mm); v1.y = __expf(v1.y - mm);
    v1.z = __expf(v1.z - mm); v1.w = __expf(v1.w - mm);

    float s = v0.x + v0.y + v0.z + v0.w + v1.x + v1.y + v1.z + v1.w;
#pragma unroll
    for (int o = 16; o > 0; o >>= 1) s += __shfl_xor_sync(0xffffffffu, s, o);
    if ((tid & 31) == 0) red[tid >> 5] = s;
    __syncthreads();
    float ss = 0.f;
#pragma unroll
    for (int i = 0; i < 8; i++) ss += red[i];
    float inv = 1.0f / ss;

    v0.x *= inv; v0.y *= inv; v0.z *= inv; v0.w *= inv;
    v1.x *= inv; v1.y *= inv; v1.z *= inv; v1.w *= inv;
    *(float4*)(p + tid * 8) = v0;
    *(float4*)(p + tid * 8 + 4) = v1;
}

// ---------------------------------------------------------------------------
// out[r,h] = tanh( sum_k cat[r,k] * W[h,k] + b[h] ),  cat = [ctx | dec]
// M = B*T = 32768, N = Hh = 1024, K = H2 = 2048. W is [Hh, H2] k-major.
// ---------------------------------------------------------------------------
__global__ void __launch_bounds__(256, 2) out_proj_kernel(
    const float* __restrict__ ctx, const float* __restrict__ dec,
    const float* __restrict__ W, const float* __restrict__ bias,
    float* __restrict__ C)
{
    __shared__ float As[BK][BM + 4];
    __shared__ float Bs[BK][BN + 4];

    const int tid = threadIdx.x;
    const int tx = tid & 15;
    const int ty = tid >> 4;
    const int m0 = blockIdx.y * BM;
    const int n0 = blockIdx.x * BN;

    ull acc[8][4];
#pragma unroll
    for (int i = 0; i < 8; i++)
#pragma unroll
        for (int j = 0; j < 4; j++) acc[i][j] = 0ull;

    for (int k0 = 0; k0 < H2; k0 += BK) {
        // A = concatenated [ctx | dec]; BK-tile never straddles the boundary
        const float* Abase = (k0 < Hh) ? ctx : dec;
        const int ka = (k0 < Hh) ? k0 : (k0 - Hh);
#pragma unroll
        for (int i = 0; i < 2; i++) {
            int lin = tid + i * 256;
            int row = lin >> 2, c4 = lin & 3;
            float4 v = *(const float4*)(Abase + (size_t)(m0 + row) * Hh + ka + c4 * 4);
            As[c4 * 4 + 0][row] = v.x;
            As[c4 * 4 + 1][row] = v.y;
            As[c4 * 4 + 2][row] = v.z;
            As[c4 * 4 + 3][row] = v.w;
        }
        // W: [N,K] k-major -> transpose-load
#pragma unroll
        for (int i = 0; i < 2; i++) {
            int lin = tid + i * 256;
            int row = lin >> 2, c4 = lin & 3;
            float4 v = *(const float4*)(W + (size_t)(n0 + row) * H2 + k0 + c4 * 4);
            Bs[c4 * 4 + 0][row] = v.x;
            Bs[c4 * 4 + 1][row] = v.y;
            Bs[c4 * 4 + 2][row] = v.z;
            Bs[c4 * 4 + 3][row] = v.w;
        }
        __syncthreads();

#pragma unroll
        for (int kk = 0; kk < BK; kk++) {
            float4 a0 = *(const float4*)&As[kk][ty * 8];
            float4 a1 = *(const float4*)&As[kk][ty * 8 + 4];
            ulonglong2 b01 = *(const ulonglong2*)&Bs[kk][tx * 8];
            ulonglong2 b23 = *(const ulonglong2*)&Bs[kk][tx * 8 + 4];
            ull bv[4] = {b01.x, b01.y, b23.x, b23.y};
            ull av[8] = {pack2(a0.x, a0.x), pack2(a0.y, a0.y),
                         pack2(a0.z, a0.z), pack2(a0.w, a0.w),
                         pack2(a1.x, a1.x), pack2(a1.y, a1.y),
                         pack2(a1.z, a1.z), pack2(a1.w, a1.w)};
#pragma unroll
            for (int i = 0; i < 8; i++)
#pragma unroll
                for (int j = 0; j < 4; j++) fma2(acc[i][j], av[i], bv[j]);
        }
        __syncthreads();
    }

#pragma unroll
    for (int i = 0; i < 8; i++) {
        float* cp = C + (size_t)(m0 + ty * 8 + i) * Hh + n0 + tx * 8;
#pragma unroll
        for (int j = 0; j < 4; j++) {
            float2 v = unpack2(acc[i][j]);
            int col = n0 + tx * 8 + 2 * j;
            v.x = tanhf(v.x + bias[col]);
            v.y = tanhf(v.y + bias[col + 1]);
            *(float2*)(cp + 2 * j) = v;
        }
    }
}

// ---------------------------------------------------------------------------
// Launch
// ---------------------------------------------------------------------------
extern "C" void kernel_launch(void* const* d_in, const int* in_sizes, int n_in,
                              void* d_out, int out_size)
{
    const float* enc  = (const float*)d_in[0];  // [B, S, H]
    const float* dec  = (const float*)d_in[1];  // [B, T, H]
    const float* W    = (const float*)d_in[2];  // [H, 2H]
    const float* bias = (const float*)d_in[3];  // [H]
    float* outp = (float*)d_out;

    const size_t OUT_N = (size_t)Bb * Tt * Hh;  // 33,554,432
    const size_t ATT_N = (size_t)Bb * Tt * Ss;  // 67,108,864

    float* ctx = nullptr;
    cudaGetSymbolAddress((void**)&ctx, g_ctx);

    // Output layout assumption: [output | attn] in reference return order.
    float* attn;
    if ((size_t)out_size >= OUT_N + ATT_N) {
        attn = outp + OUT_N;
    } else {
        cudaGetSymbolAddress((void**)&attn, g_attn_fallback);
    }

    dim3 blk(256);

    // 1) logits = dec @ enc^T  -> attn region
    gemm_kernel<1><<<dim3(Ss / BN, Tt / BM, Bb), blk>>>(
        dec, enc, attn, Hh, Hh, Hh, Ss,
        (size_t)Tt * Hh, (size_t)Ss * Hh, (size_t)Tt * Ss);

    // 2) softmax rows, in place
    softmax_kernel<<<Bb * Tt, 256>>>(attn);

    // 3) context = attn @ enc -> scratch
    gemm_kernel<0><<<dim3(Hh / BN, Tt / BM, Bb), blk>>>(
        attn, enc, ctx, Ss, Ss, Hh, Hh,
        (size_t)Tt * Ss, (size_t)Ss * Hh, (size_t)Tt * Hh);

    // 4) out = tanh([ctx|dec] @ W^T + b)
    out_proj_kernel<<<dim3(Hh / BN, (Bb * Tt) / BM, 1), blk>>>(
        ctx, dec, W, bias, outp);
}

// round 4
// speedup vs baseline: 1.8094x; 1.8094x over previous
#include <cuda_runtime.h>
#include <cuda_bf16.h>
#include <math.h>
#include <stdint.h>

#define Bb 16
#define Tt 2048
#define Ss 2048
#define Hh 1024

typedef __nv_bfloat16 bf16;
typedef unsigned long long ull;

// ---------------------------------------------------------------------------
// Device-global scratch (no runtime allocation allowed)
// ---------------------------------------------------------------------------
__device__ __align__(256) bf16 g_enc_hi[(size_t)Bb * Ss * Hh];
__device__ __align__(256) bf16 g_enc_lo[(size_t)Bb * Ss * Hh];
__device__ __align__(256) bf16 g_dec_hi[(size_t)Bb * Tt * Hh];
__device__ __align__(256) bf16 g_dec_lo[(size_t)Bb * Tt * Hh];
__device__ __align__(256) bf16 g_encT_hi[(size_t)Bb * Hh * Ss];   // [b,h,s]
__device__ __align__(256) bf16 g_encT_lo[(size_t)Bb * Hh * Ss];
__device__ __align__(256) bf16 g_P_hi[(size_t)Bb * Tt * Ss];
__device__ __align__(256) bf16 g_P_lo[(size_t)Bb * Tt * Ss];
__device__ __align__(256) bf16 g_ctx_hi[(size_t)Bb * Tt * Hh];
__device__ __align__(256) bf16 g_ctx_lo[(size_t)Bb * Tt * Hh];
__device__ __align__(256) bf16 g_W_hi[(size_t)Hh * 2 * Hh];
__device__ __align__(256) bf16 g_W_lo[(size_t)Hh * 2 * Hh];
__device__ __align__(16)  float g_attn_fallback[(size_t)Bb * Tt * Ss];

// ---------------------------------------------------------------------------
// PTX helpers (target-portable only: cp.async, ldmatrix, mma.sync)
// ---------------------------------------------------------------------------
__device__ __forceinline__ uint32_t cvta_s(const void* p) {
    uint32_t a;
    asm("{ .reg .u64 t; cvta.to.shared.u64 t, %1; cvt.u32.u64 %0, t; }"
        : "=r"(a) : "l"(p));
    return a;
}
__device__ __forceinline__ void cp16(uint32_t saddr, const void* gptr) {
    asm volatile("cp.async.cg.shared.global [%0], [%1], 16;"
                 :: "r"(saddr), "l"(__cvta_generic_to_global(gptr)));
}
__device__ __forceinline__ void cp_commit() {
    asm volatile("cp.async.commit_group;" ::: "memory");
}
template <int N>
__device__ __forceinline__ void cp_wait() {
    asm volatile("cp.async.wait_group %0;" :: "n"(N) : "memory");
}
__device__ __forceinline__ void ldsm4(uint32_t& r0, uint32_t& r1, uint32_t& r2,
                                      uint32_t& r3, uint32_t addr) {
    asm volatile("ldmatrix.sync.aligned.m8n8.x4.shared.b16 {%0,%1,%2,%3}, [%4];"
                 : "=r"(r0), "=r"(r1), "=r"(r2), "=r"(r3) : "r"(addr));
}
__device__ __forceinline__ void mma_bf16(float* c, const uint32_t* a,
                                         uint32_t b0, uint32_t b1) {
    asm volatile(
        "mma.sync.aligned.m16n8k16.row.col.f32.bf16.bf16.f32 "
        "{%0,%1,%2,%3}, {%4,%5,%6,%7}, {%8,%9}, {%0,%1,%2,%3};"
        : "+f"(c[0]), "+f"(c[1]), "+f"(c[2]), "+f"(c[3])
        : "r"(a[0]), "r"(a[1]), "r"(a[2]), "r"(a[3]), "r"(b0), "r"(b1));
}
__device__ __forceinline__ void split1(float x, bf16& h, bf16& l) {
    h = __float2bfloat16(x);
    l = __float2bfloat16(x - __bfloat162float(h));
}
__device__ __forceinline__ uint32_t pkbf(bf16 a, bf16 b) {
    __nv_bfloat162 t(a, b);
    return *reinterpret_cast<uint32_t*>(&t);
}

// ---------------------------------------------------------------------------
// Generic segmented split-bf16 MMA GEMM: D[m,n] = sum_seg A_s[m,:].B_s[n,:]
// CTA tile 128x128, 256 thr (8 warps 2x4, warp tile 64x32), K-chunks of 32,
// padded SMEM (stride 40 halves), cp.async double buffer, ldmatrix + mma.sync.
// ---------------------------------------------------------------------------
struct Seg {
    const bf16* A; const bf16* B;
    int K; int lda; int ldb;
    long long sA; long long sB;   // batch strides (elements)
};
struct GemmArgs { Seg seg[6]; int nseg; };

#define KCH 32
#define SSTRIDE 80            // bytes per SMEM row (40 halves)
#define ABUF 10240            // 128 * 80

__device__ __forceinline__ void load_chunk(uint32_t sA, uint32_t sB,
                                           const bf16* A, const bf16* Bm,
                                           int lda, int ldb, int tid) {
#pragma unroll
    for (int i = 0; i < 2; i++) {
        int lin = tid + (i << 8);
        int row = lin >> 2, seg = lin & 3;
        cp16(sA + row * SSTRIDE + seg * 16, A + (size_t)row * lda + seg * 8);
    }
#pragma unroll
    for (int i = 0; i < 2; i++) {
        int lin = tid + (i << 8);
        int row = lin >> 2, seg = lin & 3;
        cp16(sB + row * SSTRIDE + seg * 16, Bm + (size_t)row * ldb + seg * 8);
    }
}

// EPI: 0 = store fp32 C, 1 = split-bf16 store (Ch, Cl), 2 = tanh(v + bias) -> C
template <int EPI>
__global__ void __launch_bounds__(256, 2) gemm_mma(
    GemmArgs ga, float* __restrict__ C, bf16* __restrict__ Ch, bf16* __restrict__ Cl,
    const float* __restrict__ bias, int ldc, long long sC)
{
    __shared__ __align__(16) char smem[4 * ABUF];
    const uint32_t sbase = cvta_s(smem);

    const int tid = threadIdx.x;
    const int lane = tid & 31;
    const int wid = tid >> 5;
    const int wm = (wid >> 2) * 64;     // warp row offset  (0 / 64)
    const int wn = (wid & 3) * 32;      // warp col offset  (0..96)
    const int z = blockIdx.z;
    const int m0 = blockIdx.y * 128;
    const int n0 = blockIdx.x * 128;

    float acc[4][4][4];                 // [m-subtile][n8-subtile][frag]
#pragma unroll
    for (int i = 0; i < 4; i++)
#pragma unroll
        for (int j = 0; j < 4; j++)
#pragma unroll
            for (int t = 0; t < 4; t++) acc[i][j][t] = 0.f;

    int total = 0;
#pragma unroll
    for (int i = 0; i < 6; i++)
        if (i < ga.nseg) total += ga.seg[i].K / KCH;

    // ldmatrix lane addressing (within warp tile)
    const int lrow = lane & 15;         // row within 16-row subtile
    const int lcol = (lane >> 4) * 16;  // 16B column selector

    // load cursor
    int lsi = 0, lko = 0;
    {
        const Seg& sg = ga.seg[0];
        load_chunk(sbase, sbase + 2 * ABUF,
                   sg.A + z * sg.sA + (size_t)m0 * sg.lda,
                   sg.B + z * sg.sB + (size_t)n0 * sg.ldb,
                   sg.lda, sg.ldb, tid);
        cp_commit();
        lko += KCH;
        if (lko >= ga.seg[0].K) { lko = 0; lsi = 1; }
    }

    for (int gc = 0; gc < total; gc++) {
        const int st = gc & 1;
        if (gc + 1 < total) {
            const Seg& sg = ga.seg[lsi];
            load_chunk(sbase + (st ^ 1) * ABUF, sbase + 2 * ABUF + (st ^ 1) * ABUF,
                       sg.A + z * sg.sA + (size_t)m0 * sg.lda + lko,
                       sg.B + z * sg.sB + (size_t)n0 * sg.ldb + lko,
                       sg.lda, sg.ldb, tid);
            cp_commit();
            lko += KCH;
            if (lko >= ga.seg[lsi].K) { lko = 0; lsi++; }
            cp_wait<1>();
        } else {
            cp_wait<0>();
        }
        __syncthreads();

        const uint32_t aB = sbase + st * ABUF;
        const uint32_t bB = sbase + 2 * ABUF + st * ABUF;
#pragma unroll
        for (int ko = 0; ko < 2; ko++) {                 // two k16 steps
            const uint32_t kb = ko * 32 + lcol;
            uint32_t af[4][4];
#pragma unroll
            for (int mi = 0; mi < 4; mi++) {
                uint32_t addr = aB + (uint32_t)(wm + mi * 16 + lrow) * SSTRIDE + kb;
                ldsm4(af[mi][0], af[mi][1], af[mi][2], af[mi][3], addr);
            }
            uint32_t bf_[2][4];
#pragma unroll
            for (int bi = 0; bi < 2; bi++) {
                uint32_t addr = bB + (uint32_t)(wn + bi * 16 + lrow) * SSTRIDE + kb;
                ldsm4(bf_[bi][0], bf_[bi][1], bf_[bi][2], bf_[bi][3], addr);
            }
#pragma unroll
            for (int mi = 0; mi < 4; mi++)
#pragma unroll
                for (int j = 0; j < 4; j++) {
                    const int bi = j >> 1, hi = j & 1;
                    mma_bf16(acc[mi][j], af[mi], bf_[bi][hi], bf_[bi][hi + 2]);
                }
        }
        __syncthreads();
    }

    // Epilogue: thread (mi,j) owns rows r0,r0+8 and cols col,col+1
    const int rb = m0 + wm + (lane >> 2);
    const int cb = n0 + wn + (lane & 3) * 2;
#pragma unroll
    for (int mi = 0; mi < 4; mi++) {
#pragma unroll
        for (int j = 0; j < 4; j++) {
            const float* a4 = acc[mi][j];
            const int r0 = rb + mi * 16;
            const int col = cb + j * 8;
            if (EPI == 0) {
                float* p0 = C + (size_t)z * sC + (size_t)r0 * ldc + col;
                *(float2*)p0 = make_float2(a4[0], a4[1]);
                *(float2*)(p0 + 8 * (size_t)ldc) = make_float2(a4[2], a4[3]);
            } else if (EPI == 2) {
                float2 bv = *(const float2*)(bias + col);
                float* p0 = C + (size_t)r0 * ldc + col;
                *(float2*)p0 = make_float2(tanhf(a4[0] + bv.x), tanhf(a4[1] + bv.y));
                *(float2*)(p0 + 8 * (size_t)ldc) =
                    make_float2(tanhf(a4[2] + bv.x), tanhf(a4[3] + bv.y));
            } else {
                bf16 h0, l0, h1, l1;
                size_t off = (size_t)z * sC + (size_t)r0 * ldc + col;
                split1(a4[0], h0, l0); split1(a4[1], h1, l1);
                *(uint32_t*)(Ch + off) = pkbf(h0, h1);
                *(uint32_t*)(Cl + off) = pkbf(l0, l1);
                split1(a4[2], h0, l0); split1(a4[3], h1, l1);
                *(uint32_t*)(Ch + off + 8 * (size_t)ldc) = pkbf(h0, h1);
                *(uint32_t*)(Cl + off + 8 * (size_t)ldc) = pkbf(l0, l1);
            }
        }
    }
}

// ---------------------------------------------------------------------------
// fp32 -> (hi, lo) bf16 split, vectorized
// ---------------------------------------------------------------------------
__global__ void convert_split(const float4* __restrict__ in, uint2* __restrict__ hi,
                              uint2* __restrict__ lo, int n4)
{
    int i = blockIdx.x * blockDim.x + threadIdx.x;
    if (i >= n4) return;
    float4 v = in[i];
    bf16 h0, l0, h1, l1, h2, l2, h3, l3;
    split1(v.x, h0, l0); split1(v.y, h1, l1);
    split1(v.z, h2, l2); split1(v.w, h3, l3);
    hi[i] = make_uint2(pkbf(h0, h1), pkbf(h2, h3));
    lo[i] = make_uint2(pkbf(l0, l1), pkbf(l2, l3));
}

// ---------------------------------------------------------------------------
// enc [b,s,h] fp32 -> encT hi/lo bf16 [b,h,s]
// ---------------------------------------------------------------------------
__global__ void transpose_split(const float* __restrict__ enc,
                                bf16* __restrict__ Th, bf16* __restrict__ Tl)
{
    __shared__ float tile[32][33];
    const int b = blockIdx.z;
    const int s0 = blockIdx.y * 32;
    const int h0 = blockIdx.x * 32;
    const int tx = threadIdx.x & 31;
    const int ty = threadIdx.x >> 5;   // 0..7

    const float* src = enc + (size_t)b * Ss * Hh;
#pragma unroll
    for (int i = 0; i < 4; i++)
        tile[ty + i * 8][tx] = src[(size_t)(s0 + ty + i * 8) * Hh + h0 + tx];
    __syncthreads();

#pragma unroll
    for (int i = 0; i < 4; i++) {
        int hr = ty + i * 8;
        float v = tile[tx][hr];
        bf16 h, l;
        split1(v, h, l);
        size_t off = (size_t)b * Hh * Ss + (size_t)(h0 + hr) * Ss + s0 + tx;
        Th[off] = h;
        Tl[off] = l;
    }
}

// ---------------------------------------------------------------------------
// Row softmax (in place, fp32) + split-bf16 P output
// ---------------------------------------------------------------------------
__global__ void softmax_split(float* __restrict__ attn,
                              bf16* __restrict__ Ph, bf16* __restrict__ Pl)
{
    __shared__ float red[8];
    const size_t base = (size_t)blockIdx.x * Ss;
    float* p = attn + base;
    const int tid = threadIdx.x;

    float4 v0 = *(const float4*)(p + tid * 8);
    float4 v1 = *(const float4*)(p + tid * 8 + 4);

    float m = fmaxf(fmaxf(fmaxf(v0.x, v0.y), fmaxf(v0.z, v0.w)),
                    fmaxf(fmaxf(v1.x, v1.y), fmaxf(v1.z, v1.w)));
#pragma unroll
    for (int o = 16; o > 0; o >>= 1) m = fmaxf(m, __shfl_xor_sync(0xffffffffu, m, o));
    if ((tid & 31) == 0) red[tid >> 5] = m;
    __syncthreads();
    float mm = red[0];
#pragma unroll
    for (int i = 1; i < 8; i++) mm = fmaxf(mm, red[i]);
    __syncthreads();

    v0.x = __expf(v0.x - mm); v0.y = __expf(v0.y - mm);
    v0.z = __expf(v0.z - mm); v0.w = __expf(v0.w - mm);
    v1.x = __expf(v1.x - mm); v1.y = __expf(v1.y - mm);
    v1.z = __expf(v1.z - mm); v1.w = __expf(v1.w - mm);

    float s = v0.x + v0.y + v0.z + v0.w + v1.x + v1.y + v1.z + v1.w;
#pragma unroll
    for (int o = 16; o > 0; o >>= 1) s += __shfl_xor_sync(0xffffffffu, s, o);
    if ((tid & 31) == 0) red[tid >> 5] = s;
    __syncthreads();
    float ss = 0.f;
#pragma unroll
    for (int i = 0; i < 8; i++) ss += red[i];
    float inv = 1.0f / ss;

    v0.x *= inv; v0.y *= inv; v0.z *= inv; v0.w *= inv;
    v1.x *= inv; v1.y *= inv; v1.z *= inv; v1.w *= inv;
    *(float4*)(p + tid * 8) = v0;
    *(float4*)(p + tid * 8 + 4) = v1;

    float vv[8] = {v0.x, v0.y, v0.z, v0.w, v1.x, v1.y, v1.z, v1.w};
    uint32_t hp[4], lp[4];
#pragma unroll
    for (int j = 0; j < 4; j++) {
        bf16 h0, l0, h1, l1;
        split1(vv[2 * j], h0, l0);
        split1(vv[2 * j + 1], h1, l1);
        hp[j] = pkbf(h0, h1);
        lp[j] = pkbf(l0, l1);
    }
    *(uint4*)(Ph + base + tid * 8) = *(uint4*)hp;
    *(uint4*)(Pl + base + tid * 8) = *(uint4*)lp;
}

// ---------------------------------------------------------------------------
// Launch
// ---------------------------------------------------------------------------
extern "C" void kernel_launch(void* const* d_in, const int* in_sizes, int n_in,
                              void* d_out, int out_size)
{
    const float* enc  = (const float*)d_in[0];
    const float* dec  = (const float*)d_in[1];
    const float* W    = (const float*)d_in[2];
    const float* bias = (const float*)d_in[3];
    float* outp = (float*)d_out;

    const size_t OUT_N = (size_t)Bb * Tt * Hh;
    const size_t ATT_N = (size_t)Bb * Tt * Ss;

    bf16 *enc_hi, *enc_lo, *dec_hi, *dec_lo, *encT_hi, *encT_lo;
    bf16 *P_hi, *P_lo, *ctx_hi, *ctx_lo, *W_hi, *W_lo;
    cudaGetSymbolAddress((void**)&enc_hi, g_enc_hi);
    cudaGetSymbolAddress((void**)&enc_lo, g_enc_lo);
    cudaGetSymbolAddress((void**)&dec_hi, g_dec_hi);
    cudaGetSymbolAddress((void**)&dec_lo, g_dec_lo);
    cudaGetSymbolAddress((void**)&encT_hi, g_encT_hi);
    cudaGetSymbolAddress((void**)&encT_lo, g_encT_lo);
    cudaGetSymbolAddress((void**)&P_hi, g_P_hi);
    cudaGetSymbolAddress((void**)&P_lo, g_P_lo);
    cudaGetSymbolAddress((void**)&ctx_hi, g_ctx_hi);
    cudaGetSymbolAddress((void**)&ctx_lo, g_ctx_lo);
    cudaGetSymbolAddress((void**)&W_hi, g_W_hi);
    cudaGetSymbolAddress((void**)&W_lo, g_W_lo);

    float* attn;
    if ((size_t)out_size >= OUT_N + ATT_N) {
        attn = outp + OUT_N;
    } else {
        cudaGetSymbolAddress((void**)&attn, g_attn_fallback);
    }

    // 1) fp32 -> split bf16 conversions
    {
        int n4 = (int)((size_t)Bb * Ss * Hh / 4);
        convert_split<<<n4 / 256, 256>>>((const float4*)enc, (uint2*)enc_hi, (uint2*)enc_lo, n4);
        convert_split<<<n4 / 256, 256>>>((const float4*)dec, (uint2*)dec_hi, (uint2*)dec_lo, n4);
        int w4 = (int)((size_t)Hh * 2 * Hh / 4);
        convert_split<<<w4 / 256, 256>>>((const float4*)W, (uint2*)W_hi, (uint2*)W_lo, w4);
    }
    // 2) enc transpose+split for GEMM2's B
    transpose_split<<<dim3(Hh / 32, Ss / 32, Bb), 256>>>(enc, encT_hi, encT_lo);

    // 3) logits = dec . enc^T   (split: hh + lh + hl)
    {
        GemmArgs ga;
        ga.nseg = 3;
        long long sD = (long long)Tt * Hh, sE = (long long)Ss * Hh;
        ga.seg[0] = {dec_hi, enc_hi, Hh, Hh, Hh, sD, sE};
        ga.seg[1] = {dec_lo, enc_hi, Hh, Hh, Hh, sD, sE};
        ga.seg[2] = {dec_hi, enc_lo, Hh, Hh, Hh, sD, sE};
        gemm_mma<0><<<dim3(Ss / 128, Tt / 128, Bb), 256>>>(
            ga, attn, nullptr, nullptr, nullptr, Ss, (long long)Tt * Ss);
    }

    // 4) softmax + P split
    softmax_split<<<Bb * Tt, 256>>>(attn, P_hi, P_lo);

    // 5) ctx = P . enc  (B = encT, k = s), epilogue writes ctx hi/lo
    {
        GemmArgs ga;
        ga.nseg = 3;
        long long sP = (long long)Tt * Ss, sT = (long long)Hh * Ss;
        ga.seg[0] = {P_hi, encT_hi, Ss, Ss, Ss, sP, sT};
        ga.seg[1] = {P_lo, encT_hi, Ss, Ss, Ss, sP, sT};
        ga.seg[2] = {P_hi, encT_lo, Ss, Ss, Ss, sP, sT};
        gemm_mma<1><<<dim3(Hh / 128, Tt / 128, Bb), 256>>>(
            ga, nullptr, ctx_hi, ctx_lo, nullptr, Hh, (long long)Tt * Hh);
    }

    // 6) out = tanh([ctx|dec] . W^T + b); cat split over 6 segments
    {
        GemmArgs ga;
        ga.nseg = 6;
        const int ldw = 2 * Hh;
        ga.seg[0] = {ctx_hi, W_hi,        Hh, Hh, ldw, 0, 0};
        ga.seg[1] = {dec_hi, W_hi + Hh,   Hh, Hh, ldw, 0, 0};
        ga.seg[2] = {ctx_lo, W_hi,        Hh, Hh, ldw, 0, 0};
        ga.seg[3] = {dec_lo, W_hi + Hh,   Hh, Hh, ldw, 0, 0};
        ga.seg[4] = {ctx_hi, W_lo,        Hh, Hh, ldw, 0, 0};
        ga.seg[5] = {dec_hi, W_lo + Hh,   Hh, Hh, ldw, 0, 0};
        gemm_mma<2><<<dim3(Hh / 128, (Bb * Tt) / 128, 1), 256>>>(
            ga, outp, nullptr, nullptr, bias, Hh, 0);
    }
}

// round 8
// speedup vs baseline: 1.8524x; 1.0237x over previous
#include <cuda_runtime.h>
#include <cuda_bf16.h>
#include <math.h>
#include <stdint.h>

#define Bb 16
#define Tt 2048
#define Ss 2048
#define Hh 1024

typedef __nv_bfloat16 bf16;
typedef unsigned long long ull;

// ---------------------------------------------------------------------------
// Device-global scratch (no runtime allocation allowed)
// ---------------------------------------------------------------------------
__device__ __align__(256) bf16 g_enc_hi[(size_t)Bb * Ss * Hh];
__device__ __align__(256) bf16 g_enc_lo[(size_t)Bb * Ss * Hh];
__device__ __align__(256) bf16 g_dec_hi[(size_t)Bb * Tt * Hh];
__device__ __align__(256) bf16 g_dec_lo[(size_t)Bb * Tt * Hh];
__device__ __align__(256) bf16 g_encT_hi[(size_t)Bb * Hh * Ss];   // [b,h,s]
__device__ __align__(256) bf16 g_encT_lo[(size_t)Bb * Hh * Ss];
__device__ __align__(256) bf16 g_P_hi[(size_t)Bb * Tt * Ss];
__device__ __align__(256) bf16 g_P_lo[(size_t)Bb * Tt * Ss];
__device__ __align__(256) bf16 g_ctx_hi[(size_t)Bb * Tt * Hh];
__device__ __align__(256) bf16 g_ctx_lo[(size_t)Bb * Tt * Hh];
__device__ __align__(256) bf16 g_W_hi[(size_t)Hh * 2 * Hh];
__device__ __align__(256) bf16 g_W_lo[(size_t)Hh * 2 * Hh];
__device__ __align__(16)  float g_attn_fallback[(size_t)Bb * Tt * Ss];

// ---------------------------------------------------------------------------
// PTX helpers (target-portable only: cp.async, ldmatrix, mma.sync)
// ---------------------------------------------------------------------------
__device__ __forceinline__ uint32_t cvta_s(const void* p) {
    uint32_t a;
    asm("{ .reg .u64 t; cvta.to.shared.u64 t, %1; cvt.u32.u64 %0, t; }"
        : "=r"(a) : "l"(p));
    return a;
}
__device__ __forceinline__ void cp16(uint32_t saddr, const void* gptr) {
    asm volatile("cp.async.cg.shared.global [%0], [%1], 16;"
                 :: "r"(saddr), "l"(__cvta_generic_to_global(gptr)));
}
__device__ __forceinline__ void cp_commit() {
    asm volatile("cp.async.commit_group;" ::: "memory");
}
template <int N>
__device__ __forceinline__ void cp_wait() {
    asm volatile("cp.async.wait_group %0;" :: "n"(N) : "memory");
}
__device__ __forceinline__ void ldsm4(uint32_t& r0, uint32_t& r1, uint32_t& r2,
                                      uint32_t& r3, uint32_t addr) {
    asm volatile("ldmatrix.sync.aligned.m8n8.x4.shared.b16 {%0,%1,%2,%3}, [%4];"
                 : "=r"(r0), "=r"(r1), "=r"(r2), "=r"(r3) : "r"(addr));
}
__device__ __forceinline__ void mma_bf16(float* c, const uint32_t* a,
                                         uint32_t b0, uint32_t b1) {
    asm volatile(
        "mma.sync.aligned.m16n8k16.row.col.f32.bf16.bf16.f32 "
        "{%0,%1,%2,%3}, {%4,%5,%6,%7}, {%8,%9}, {%0,%1,%2,%3};"
        : "+f"(c[0]), "+f"(c[1]), "+f"(c[2]), "+f"(c[3])
        : "r"(a[0]), "r"(a[1]), "r"(a[2]), "r"(a[3]), "r"(b0), "r"(b1));
}
__device__ __forceinline__ void split1(float x, bf16& h, bf16& l) {
    h = __float2bfloat16(x);
    l = __float2bfloat16(x - __bfloat162float(h));
}
__device__ __forceinline__ uint32_t pkbf(bf16 a, bf16 b) {
    __nv_bfloat162 t(a, b);
    return *reinterpret_cast<uint32_t*>(&t);
}

// ---------------------------------------------------------------------------
// Generic segmented split-bf16 MMA GEMM: D[m,n] = sum_seg A_s[m,:].B_s[n,:]
// CTA tile 128x128, 256 thr (8 warps 2x4, warp tile 64x32), K-chunks of 32,
// padded SMEM (stride 40 halves), 4-stage cp.async pipeline (depth-3 prefetch,
// ONE __syncthreads per chunk), ldmatrix + mma.sync.
// ---------------------------------------------------------------------------
struct Seg {
    const bf16* A; const bf16* B;
    int K; int lda; int ldb;
    long long sA; long long sB;   // batch strides (elements)
};
struct GemmArgs { Seg seg[6]; int nseg; };

#define KCH 32
#define SSTRIDE 80            // bytes per SMEM row (40 halves)
#define ABUF 10240            // 128 * 80
#define NSTAGE 4
#define SMEM_DYN (2 * NSTAGE * ABUF)   // 81920

__device__ __forceinline__ void load_chunk(uint32_t sA, uint32_t sB,
                                           const bf16* A, const bf16* Bm,
                                           int lda, int ldb, int tid) {
#pragma unroll
    for (int i = 0; i < 2; i++) {
        int lin = tid + (i << 8);
        int row = lin >> 2, seg = lin & 3;
        cp16(sA + row * SSTRIDE + seg * 16, A + (size_t)row * lda + seg * 8);
    }
#pragma unroll
    for (int i = 0; i < 2; i++) {
        int lin = tid + (i << 8);
        int row = lin >> 2, seg = lin & 3;
        cp16(sB + row * SSTRIDE + seg * 16, Bm + (size_t)row * ldb + seg * 8);
    }
}

// EPI: 0 = store fp32 C, 1 = split-bf16 store (Ch, Cl), 2 = tanh(v + bias) -> C
template <int EPI>
__global__ void __launch_bounds__(256, 2) gemm_mma(
    GemmArgs ga, float* __restrict__ C, bf16* __restrict__ Ch, bf16* __restrict__ Cl,
    const float* __restrict__ bias, int ldc, long long sC)
{
    extern __shared__ __align__(16) char smem[];
    const uint32_t sbase = cvta_s(smem);

    const int tid = threadIdx.x;
    const int lane = tid & 31;
    const int wid = tid >> 5;
    const int wm = (wid >> 2) * 64;     // warp row offset  (0 / 64)
    const int wn = (wid & 3) * 32;      // warp col offset  (0..96)
    const int z = blockIdx.z;
    const int m0 = blockIdx.y * 128;
    const int n0 = blockIdx.x * 128;

    float acc[4][4][4];                 // [m-subtile][n8-subtile][frag]
#pragma unroll
    for (int i = 0; i < 4; i++)
#pragma unroll
        for (int j = 0; j < 4; j++)
#pragma unroll
            for (int t = 0; t < 4; t++) acc[i][j][t] = 0.f;

    int total = 0;
#pragma unroll
    for (int i = 0; i < 6; i++)
        if (i < ga.nseg) total += ga.seg[i].K / KCH;

    // ldmatrix lane addressing (within warp tile)
    const int lrow = lane & 15;         // row within 16-row subtile
    const int lcol = (lane >> 4) * 16;  // 16B column selector

    // load cursor
    int lsi = 0, lko = 0;
    // Prologue: prefetch chunks 0..2 into stages 0..2
#pragma unroll
    for (int pf = 0; pf < NSTAGE - 1; pf++) {
        if (pf < total) {
            const Seg& sg = ga.seg[lsi];
            load_chunk(sbase + pf * ABUF, sbase + (NSTAGE + pf) * ABUF,
                       sg.A + z * sg.sA + (size_t)m0 * sg.lda + lko,
                       sg.B + z * sg.sB + (size_t)n0 * sg.ldb + lko,
                       sg.lda, sg.ldb, tid);
            cp_commit();
            lko += KCH;
            if (lko >= ga.seg[lsi].K) { lko = 0; lsi++; }
        }
    }

    for (int gc = 0; gc < total; gc++) {
        const int st = gc & (NSTAGE - 1);
        // chunk gc must have landed; allow the newest in-flight chunks to fly
        if (gc + 2 < total)      cp_wait<2>();
        else if (gc + 1 < total) cp_wait<1>();
        else                     cp_wait<0>();
        __syncthreads();   // data visible + all warps done with the slot reused below

        if (gc + NSTAGE - 1 < total) {
            const int ls = (gc + NSTAGE - 1) & (NSTAGE - 1);
            const Seg& sg = ga.seg[lsi];
            load_chunk(sbase + ls * ABUF, sbase + (NSTAGE + ls) * ABUF,
                       sg.A + z * sg.sA + (size_t)m0 * sg.lda + lko,
                       sg.B + z * sg.sB + (size_t)n0 * sg.ldb + lko,
                       sg.lda, sg.ldb, tid);
            cp_commit();
            lko += KCH;
            if (lko >= ga.seg[lsi].K) { lko = 0; lsi++; }
        }

        const uint32_t aB = sbase + st * ABUF;
        const uint32_t bB = sbase + (NSTAGE + st) * ABUF;
#pragma unroll
        for (int ko = 0; ko < 2; ko++) {                 // two k16 steps
            const uint32_t kb = ko * 32 + lcol;
            uint32_t af[4][4];
#pragma unroll
            for (int mi = 0; mi < 4; mi++) {
                uint32_t addr = aB + (uint32_t)(wm + mi * 16 + lrow) * SSTRIDE + kb;
                ldsm4(af[mi][0], af[mi][1], af[mi][2], af[mi][3], addr);
            }
            uint32_t bf_[2][4];
#pragma unroll
            for (int bi = 0; bi < 2; bi++) {
                uint32_t addr = bB + (uint32_t)(wn + bi * 16 + lrow) * SSTRIDE + kb;
                ldsm4(bf_[bi][0], bf_[bi][1], bf_[bi][2], bf_[bi][3], addr);
            }
#pragma unroll
            for (int mi = 0; mi < 4; mi++)
#pragma unroll
                for (int j = 0; j < 4; j++) {
                    const int bi = j >> 1, hi = j & 1;
                    mma_bf16(acc[mi][j], af[mi], bf_[bi][hi], bf_[bi][hi + 2]);
                }
        }
    }

    // Epilogue: thread (mi,j) owns rows r0,r0+8 and cols col,col+1
    const int rb = m0 + wm + (lane >> 2);
    const int cb = n0 + wn + (lane & 3) * 2;
#pragma unroll
    for (int mi = 0; mi < 4; mi++) {
#pragma unroll
        for (int j = 0; j < 4; j++) {
            const float* a4 = acc[mi][j];
            const int r0 = rb + mi * 16;
            const int col = cb + j * 8;
            if (EPI == 0) {
                float* p0 = C + (size_t)z * sC + (size_t)r0 * ldc + col;
                *(float2*)p0 = make_float2(a4[0], a4[1]);
                *(float2*)(p0 + 8 * (size_t)ldc) = make_float2(a4[2], a4[3]);
            } else if (EPI == 2) {
                float2 bv = *(const float2*)(bias + col);
                float* p0 = C + (size_t)r0 * ldc + col;
                *(float2*)p0 = make_float2(tanhf(a4[0] + bv.x), tanhf(a4[1] + bv.y));
                *(float2*)(p0 + 8 * (size_t)ldc) =
                    make_float2(tanhf(a4[2] + bv.x), tanhf(a4[3] + bv.y));
            } else {
                bf16 h0, l0, h1, l1;
                size_t off = (size_t)z * sC + (size_t)r0 * ldc + col;
                split1(a4[0], h0, l0); split1(a4[1], h1, l1);
                *(uint32_t*)(Ch + off) = pkbf(h0, h1);
                *(uint32_t*)(Cl + off) = pkbf(l0, l1);
                split1(a4[2], h0, l0); split1(a4[3], h1, l1);
                *(uint32_t*)(Ch + off + 8 * (size_t)ldc) = pkbf(h0, h1);
                *(uint32_t*)(Cl + off + 8 * (size_t)ldc) = pkbf(l0, l1);
            }
        }
    }
}

// ---------------------------------------------------------------------------
// fp32 -> (hi, lo) bf16 split, vectorized
// ---------------------------------------------------------------------------
__global__ void convert_split(const float4* __restrict__ in, uint2* __restrict__ hi,
                              uint2* __restrict__ lo, int n4)
{
    int i = blockIdx.x * blockDim.x + threadIdx.x;
    if (i >= n4) return;
    float4 v = in[i];
    bf16 h0, l0, h1, l1, h2, l2, h3, l3;
    split1(v.x, h0, l0); split1(v.y, h1, l1);
    split1(v.z, h2, l2); split1(v.w, h3, l3);
    hi[i] = make_uint2(pkbf(h0, h1), pkbf(h2, h3));
    lo[i] = make_uint2(pkbf(l0, l1), pkbf(l2, l3));
}

// ---------------------------------------------------------------------------
// enc [b,s,h] fp32 -> encT hi/lo bf16 [b,h,s]
// ---------------------------------------------------------------------------
__global__ void transpose_split(const float* __restrict__ enc,
                                bf16* __restrict__ Th, bf16* __restrict__ Tl)
{
    __shared__ float tile[32][33];
    const int b = blockIdx.z;
    const int s0 = blockIdx.y * 32;
    const int h0 = blockIdx.x * 32;
    const int tx = threadIdx.x & 31;
    const int ty = threadIdx.x >> 5;   // 0..7

    const float* src = enc + (size_t)b * Ss * Hh;
#pragma unroll
    for (int i = 0; i < 4; i++)
        tile[ty + i * 8][tx] = src[(size_t)(s0 + ty + i * 8) * Hh + h0 + tx];
    __syncthreads();

#pragma unroll
    for (int i = 0; i < 4; i++) {
        int hr = ty + i * 8;
        float v = tile[tx][hr];
        bf16 h, l;
        split1(v, h, l);
        size_t off = (size_t)b * Hh * Ss + (size_t)(h0 + hr) * Ss + s0 + tx;
        Th[off] = h;
        Tl[off] = l;
    }
}

// ---------------------------------------------------------------------------
// Row softmax (in place, fp32) + split-bf16 P output
// ---------------------------------------------------------------------------
__global__ void softmax_split(float* __restrict__ attn,
                              bf16* __restrict__ Ph, bf16* __restrict__ Pl)
{
    __shared__ float red[8];
    const size_t base = (size_t)blockIdx.x * Ss;
    float* p = attn + base;
    const int tid = threadIdx.x;

    float4 v0 = *(const float4*)(p + tid * 8);
    float4 v1 = *(const float4*)(p + tid * 8 + 4);

    float m = fmaxf(fmaxf(fmaxf(v0.x, v0.y), fmaxf(v0.z, v0.w)),
                    fmaxf(fmaxf(v1.x, v1.y), fmaxf(v1.z, v1.w)));
#pragma unroll
    for (int o = 16; o > 0; o >>= 1) m = fmaxf(m, __shfl_xor_sync(0xffffffffu, m, o));
    if ((tid & 31) == 0) red[tid >> 5] = m;
    __syncthreads();
    float mm = red[0];
#pragma unroll
    for (int i = 1; i < 8; i++) mm = fmaxf(mm, red[i]);
    __syncthreads();

    v0.x = __expf(v0.x - mm); v0.y = __expf(v0.y - mm);
    v0.z = __expf(v0.z - mm); v0.w = __expf(v0.w - mm);
    v1.x = __expf(v1.x - mm); v1.y = __expf(v1.y - mm);
    v1.z = __expf(v1.z - mm); v1.w = __expf(v1.w - mm);

    float s = v0.x + v0.y + v0.z + v0.w + v1.x + v1.y + v1.z + v1.w;
#pragma unroll
    for (int o = 16; o > 0; o >>= 1) s += __shfl_xor_sync(0xffffffffu, s, o);
    if ((tid & 31) == 0) red[tid >> 5] = s;
    __syncthreads();
    float ss = 0.f;
#pragma unroll
    for (int i = 0; i < 8; i++) ss += red[i];
    float inv = 1.0f / ss;

    v0.x *= inv; v0.y *= inv; v0.z *= inv; v0.w *= inv;
    v1.x *= inv; v1.y *= inv; v1.z *= inv; v1.w *= inv;
    *(float4*)(p + tid * 8) = v0;
    *(float4*)(p + tid * 8 + 4) = v1;

    float vv[8] = {v0.x, v0.y, v0.z, v0.w, v1.x, v1.y, v1.z, v1.w};
    uint32_t hp[4], lp[4];
#pragma unroll
    for (int j = 0; j < 4; j++) {
        bf16 h0, l0, h1, l1;
        split1(vv[2 * j], h0, l0);
        split1(vv[2 * j + 1], h1, l1);
        hp[j] = pkbf(h0, h1);
        lp[j] = pkbf(l0, l1);
    }
    *(uint4*)(Ph + base + tid * 8) = *(uint4*)hp;
    *(uint4*)(Pl + base + tid * 8) = *(uint4*)lp;
}

// ---------------------------------------------------------------------------
// Launch
// ---------------------------------------------------------------------------
extern "C" void kernel_launch(void* const* d_in, const int* in_sizes, int n_in,
                              void* d_out, int out_size)
{
    const float* enc  = (const float*)d_in[0];
    const float* dec  = (const float*)d_in[1];
    const float* W    = (const float*)d_in[2];
    const float* bias = (const float*)d_in[3];
    float* outp = (float*)d_out;

    const size_t OUT_N = (size_t)Bb * Tt * Hh;
    const size_t ATT_N = (size_t)Bb * Tt * Ss;

    bf16 *enc_hi, *enc_lo, *dec_hi, *dec_lo, *encT_hi, *encT_lo;
    bf16 *P_hi, *P_lo, *ctx_hi, *ctx_lo, *W_hi, *W_lo;
    cudaGetSymbolAddress((void**)&enc_hi, g_enc_hi);
    cudaGetSymbolAddress((void**)&enc_lo, g_enc_lo);
    cudaGetSymbolAddress((void**)&dec_hi, g_dec_hi);
    cudaGetSymbolAddress((void**)&dec_lo, g_dec_lo);
    cudaGetSymbolAddress((void**)&encT_hi, g_encT_hi);
    cudaGetSymbolAddress((void**)&encT_lo, g_encT_lo);
    cudaGetSymbolAddress((void**)&P_hi, g_P_hi);
    cudaGetSymbolAddress((void**)&P_lo, g_P_lo);
    cudaGetSymbolAddress((void**)&ctx_hi, g_ctx_hi);
    cudaGetSymbolAddress((void**)&ctx_lo, g_ctx_lo);
    cudaGetSymbolAddress((void**)&W_hi, g_W_hi);
    cudaGetSymbolAddress((void**)&W_lo, g_W_lo);

    float* attn;
    if ((size_t)out_size >= OUT_N + ATT_N) {
        attn = outp + OUT_N;
    } else {
        cudaGetSymbolAddress((void**)&attn, g_attn_fallback);
    }

    cudaFuncSetAttribute(gemm_mma<0>, cudaFuncAttributeMaxDynamicSharedMemorySize, SMEM_DYN);
    cudaFuncSetAttribute(gemm_mma<1>, cudaFuncAttributeMaxDynamicSharedMemorySize, SMEM_DYN);
    cudaFuncSetAttribute(gemm_mma<2>, cudaFuncAttributeMaxDynamicSharedMemorySize, SMEM_DYN);

    // 1) fp32 -> split bf16 conversions
    {
        int n4 = (int)((size_t)Bb * Ss * Hh / 4);
        convert_split<<<n4 / 256, 256>>>((const float4*)enc, (uint2*)enc_hi, (uint2*)enc_lo, n4);
        convert_split<<<n4 / 256, 256>>>((const float4*)dec, (uint2*)dec_hi, (uint2*)dec_lo, n4);
        int w4 = (int)((size_t)Hh * 2 * Hh / 4);
        convert_split<<<w4 / 256, 256>>>((const float4*)W, (uint2*)W_hi, (uint2*)W_lo, w4);
    }
    // 2) enc transpose+split for GEMM2's B
    transpose_split<<<dim3(Hh / 32, Ss / 32, Bb), 256>>>(enc, encT_hi, encT_lo);

    // 3) logits = dec . enc^T   (split: hh + lh + hl)
    {
        GemmArgs ga;
        ga.nseg = 3;
        long long sD = (long long)Tt * Hh, sE = (long long)Ss * Hh;
        ga.seg[0] = {dec_hi, enc_hi, Hh, Hh, Hh, sD, sE};
        ga.seg[1] = {dec_lo, enc_hi, Hh, Hh, Hh, sD, sE};
        ga.seg[2] = {dec_hi, enc_lo, Hh, Hh, Hh, sD, sE};
        gemm_mma<0><<<dim3(Ss / 128, Tt / 128, Bb), 256, SMEM_DYN>>>(
            ga, attn, nullptr, nullptr, nullptr, Ss, (long long)Tt * Ss);
    }

    // 4) softmax + P split
    softmax_split<<<Bb * Tt, 256>>>(attn, P_hi, P_lo);

    // 5) ctx = P . enc  (B = encT, k = s), epilogue writes ctx hi/lo
    {
        GemmArgs ga;
        ga.nseg = 3;
        long long sP = (long long)Tt * Ss, sT = (long long)Hh * Ss;
        ga.seg[0] = {P_hi, encT_hi, Ss, Ss, Ss, sP, sT};
        ga.seg[1] = {P_lo, encT_hi, Ss, Ss, Ss, sP, sT};
        ga.seg[2] = {P_hi, encT_lo, Ss, Ss, Ss, sP, sT};
        gemm_mma<1><<<dim3(Hh / 128, Tt / 128, Bb), 256, SMEM_DYN>>>(
            ga, nullptr, ctx_hi, ctx_lo, nullptr, Hh, (long long)Tt * Hh);
    }

    // 6) out = tanh([ctx|dec] . W^T + b); cat split over 6 segments
    {
        GemmArgs ga;
        ga.nseg = 6;
        const int ldw = 2 * Hh;
        ga.seg[0] = {ctx_hi, W_hi,        Hh, Hh, ldw, 0, 0};
        ga.seg[1] = {dec_hi, W_hi + Hh,   Hh, Hh, ldw, 0, 0};
        ga.seg[2] = {ctx_lo, W_hi,        Hh, Hh, ldw, 0, 0};
        ga.seg[3] = {dec_lo, W_hi + Hh,   Hh, Hh, ldw, 0, 0};
        ga.seg[4] = {ctx_hi, W_lo,        Hh, Hh, ldw, 0, 0};
        ga.seg[5] = {dec_hi, W_lo + Hh,   Hh, Hh, ldw, 0, 0};
        gemm_mma<2><<<dim3(Hh / 128, (Bb * Tt) / 128, 1), 256, SMEM_DYN>>>(
            ga, outp, nullptr, nullptr, bias, Hh, 0);
    }
}

// round 10
// speedup vs baseline: 1.8884x; 1.0194x over previous
#include <cuda_runtime.h>
#include <cuda_bf16.h>
#include <math.h>
#include <stdint.h>

#define Bb 16
#define Tt 2048
#define Ss 2048
#define Hh 1024

typedef __nv_bfloat16 bf16;
typedef unsigned long long ull;

// ---------------------------------------------------------------------------
// Device-global scratch (no runtime allocation allowed)
// ---------------------------------------------------------------------------
__device__ __align__(256) bf16 g_enc_hi[(size_t)Bb * Ss * Hh];
__device__ __align__(256) bf16 g_enc_lo[(size_t)Bb * Ss * Hh];
__device__ __align__(256) bf16 g_dec_hi[(size_t)Bb * Tt * Hh];
__device__ __align__(256) bf16 g_dec_lo[(size_t)Bb * Tt * Hh];
__device__ __align__(256) bf16 g_encT_hi[(size_t)Bb * Hh * Ss];   // [b,h,s]
__device__ __align__(256) bf16 g_encT_lo[(size_t)Bb * Hh * Ss];
__device__ __align__(256) bf16 g_P_hi[(size_t)Bb * Tt * Ss];
__device__ __align__(256) bf16 g_P_lo[(size_t)Bb * Tt * Ss];
__device__ __align__(256) bf16 g_ctx_hi[(size_t)Bb * Tt * Hh];
__device__ __align__(256) bf16 g_ctx_lo[(size_t)Bb * Tt * Hh];
__device__ __align__(256) bf16 g_W_hi[(size_t)Hh * 2 * Hh];
__device__ __align__(256) bf16 g_W_lo[(size_t)Hh * 2 * Hh];
__device__ __align__(16)  float g_attn_fallback[(size_t)Bb * Tt * Ss];

// ---------------------------------------------------------------------------
// PTX helpers (target-portable only: cp.async, ldmatrix, mma.sync)
// ---------------------------------------------------------------------------
__device__ __forceinline__ uint32_t cvta_s(const void* p) {
    uint32_t a;
    asm("{ .reg .u64 t; cvta.to.shared.u64 t, %1; cvt.u32.u64 %0, t; }"
        : "=r"(a) : "l"(p));
    return a;
}
__device__ __forceinline__ void cp16(uint32_t saddr, const void* gptr) {
    asm volatile("cp.async.cg.shared.global [%0], [%1], 16;"
                 :: "r"(saddr), "l"(__cvta_generic_to_global(gptr)));
}
__device__ __forceinline__ void cp_commit() {
    asm volatile("cp.async.commit_group;" ::: "memory");
}
template <int N>
__device__ __forceinline__ void cp_wait() {
    asm volatile("cp.async.wait_group %0;" :: "n"(N) : "memory");
}
__device__ __forceinline__ void ldsm4(uint32_t& r0, uint32_t& r1, uint32_t& r2,
                                      uint32_t& r3, uint32_t addr) {
    asm volatile("ldmatrix.sync.aligned.m8n8.x4.shared.b16 {%0,%1,%2,%3}, [%4];"
                 : "=r"(r0), "=r"(r1), "=r"(r2), "=r"(r3) : "r"(addr));
}
__device__ __forceinline__ void mma_bf16(float* c, const uint32_t* a,
                                         uint32_t b0, uint32_t b1) {
    asm volatile(
        "mma.sync.aligned.m16n8k16.row.col.f32.bf16.bf16.f32 "
        "{%0,%1,%2,%3}, {%4,%5,%6,%7}, {%8,%9}, {%0,%1,%2,%3};"
        : "+f"(c[0]), "+f"(c[1]), "+f"(c[2]), "+f"(c[3])
        : "r"(a[0]), "r"(a[1]), "r"(a[2]), "r"(a[3]), "r"(b0), "r"(b1));
}
__device__ __forceinline__ void split1(float x, bf16& h, bf16& l) {
    h = __float2bfloat16(x);
    l = __float2bfloat16(x - __bfloat162float(h));
}
__device__ __forceinline__ uint32_t pkbf(bf16 a, bf16 b) {
    __nv_bfloat162 t(a, b);
    return *reinterpret_cast<uint32_t*>(&t);
}

// ---------------------------------------------------------------------------
// Generic segmented split-bf16 MMA GEMM: D[m,n] = sum_seg A_s[m,:].B_s[n,:]
// CTA tile 128x128, 128 thr (4 warps 2x2, warp tile 64x64), K-chunks of 32,
// padded SMEM (stride 40 halves), 4-stage cp.async pipeline, ldmatrix+mma.sync.
// ---------------------------------------------------------------------------
struct Seg {
    const bf16* A; const bf16* B;
    int K; int lda; int ldb;
    long long sA; long long sB;   // batch strides (elements)
};
struct GemmArgs { Seg seg[6]; int nseg; };

#define KCH 32
#define SSTRIDE 80            // bytes per SMEM row (40 halves)
#define ABUF 10240            // 128 * 80
#define NSTAGE 4
#define SMEM_DYN (2 * NSTAGE * ABUF)   // 81920

__device__ __forceinline__ void load_chunk(uint32_t sA, uint32_t sB,
                                           const bf16* A, const bf16* Bm,
                                           int lda, int ldb, int tid) {
#pragma unroll
    for (int i = 0; i < 4; i++) {
        int lin = tid + (i << 7);
        int row = lin >> 2, seg = lin & 3;
        cp16(sA + row * SSTRIDE + seg * 16, A + (size_t)row * lda + seg * 8);
    }
#pragma unroll
    for (int i = 0; i < 4; i++) {
        int lin = tid + (i << 7);
        int row = lin >> 2, seg = lin & 3;
        cp16(sB + row * SSTRIDE + seg * 16, Bm + (size_t)row * ldb + seg * 8);
    }
}

// EPI: 0 = store fp32 C, 1 = split-bf16 store (Ch, Cl), 2 = tanh(v + bias) -> C
template <int EPI>
__global__ void __launch_bounds__(128, 2) gemm_mma(
    GemmArgs ga, float* __restrict__ C, bf16* __restrict__ Ch, bf16* __restrict__ Cl,
    const float* __restrict__ bias, int ldc, long long sC)
{
    extern __shared__ __align__(16) char smem[];
    const uint32_t sbase = cvta_s(smem);

    const int tid = threadIdx.x;
    const int lane = tid & 31;
    const int wid = tid >> 5;           // 0..3
    const int wm = (wid >> 1) * 64;     // warp row offset  (0 / 64)
    const int wn = (wid & 1) * 64;      // warp col offset  (0 / 64)
    const int z = blockIdx.z;
    const int m0 = blockIdx.y * 128;
    const int n0 = blockIdx.x * 128;

    float acc[4][8][4];                 // [m16-subtile][n8-subtile][frag]
#pragma unroll
    for (int i = 0; i < 4; i++)
#pragma unroll
        for (int j = 0; j < 8; j++)
#pragma unroll
            for (int t = 0; t < 4; t++) acc[i][j][t] = 0.f;

    int total = 0;
#pragma unroll
    for (int i = 0; i < 6; i++)
        if (i < ga.nseg) total += ga.seg[i].K / KCH;

    // ldmatrix lane addressing (within warp tile)
    const int lrow = lane & 15;         // row within 16-row subtile
    const int lcol = (lane >> 4) * 16;  // 16B column selector

    // load cursor
    int lsi = 0, lko = 0;
    // Prologue: prefetch chunks 0..2 into stages 0..2
#pragma unroll
    for (int pf = 0; pf < NSTAGE - 1; pf++) {
        if (pf < total) {
            const Seg& sg = ga.seg[lsi];
            load_chunk(sbase + pf * ABUF, sbase + (NSTAGE + pf) * ABUF,
                       sg.A + z * sg.sA + (size_t)m0 * sg.lda + lko,
                       sg.B + z * sg.sB + (size_t)n0 * sg.ldb + lko,
                       sg.lda, sg.ldb, tid);
            cp_commit();
            lko += KCH;
            if (lko >= ga.seg[lsi].K) { lko = 0; lsi++; }
        }
    }

    for (int gc = 0; gc < total; gc++) {
        const int st = gc & (NSTAGE - 1);
        // chunk gc must have landed; allow the newest in-flight chunks to fly
        if (gc + 2 < total)      cp_wait<2>();
        else if (gc + 1 < total) cp_wait<1>();
        else                     cp_wait<0>();
        __syncthreads();   // data visible + all warps done with the slot reused below

        if (gc + NSTAGE - 1 < total) {
            const int ls = (gc + NSTAGE - 1) & (NSTAGE - 1);
            const Seg& sg = ga.seg[lsi];
            load_chunk(sbase + ls * ABUF, sbase + (NSTAGE + ls) * ABUF,
                       sg.A + z * sg.sA + (size_t)m0 * sg.lda + lko,
                       sg.B + z * sg.sB + (size_t)n0 * sg.ldb + lko,
                       sg.lda, sg.ldb, tid);
            cp_commit();
            lko += KCH;
            if (lko >= ga.seg[lsi].K) { lko = 0; lsi++; }
        }

        const uint32_t aB = sbase + st * ABUF;
        const uint32_t bB = sbase + (NSTAGE + st) * ABUF;
#pragma unroll
        for (int ko = 0; ko < 2; ko++) {                 // two k16 steps
            const uint32_t kb = ko * 32 + lcol;
            uint32_t af[4][4];
#pragma unroll
            for (int mi = 0; mi < 4; mi++) {
                uint32_t addr = aB + (uint32_t)(wm + mi * 16 + lrow) * SSTRIDE + kb;
                ldsm4(af[mi][0], af[mi][1], af[mi][2], af[mi][3], addr);
            }
            uint32_t bf_[4][4];
#pragma unroll
            for (int bi = 0; bi < 4; bi++) {
                uint32_t addr = bB + (uint32_t)(wn + bi * 16 + lrow) * SSTRIDE + kb;
                ldsm4(bf_[bi][0], bf_[bi][1], bf_[bi][2], bf_[bi][3], addr);
            }
#pragma unroll
            for (int mi = 0; mi < 4; mi++)
#pragma unroll
                for (int j = 0; j < 8; j++) {
                    const int bi = j >> 1, hi = j & 1;
                    mma_bf16(acc[mi][j], af[mi], bf_[bi][hi], bf_[bi][hi + 2]);
                }
        }
    }

    // Epilogue: thread (mi,j) owns rows r0,r0+8 and cols col,col+1
    const int rb = m0 + wm + (lane >> 2);
    const int cb = n0 + wn + (lane & 3) * 2;
#pragma unroll
    for (int mi = 0; mi < 4; mi++) {
#pragma unroll
        for (int j = 0; j < 8; j++) {
            const float* a4 = acc[mi][j];
            const int r0 = rb + mi * 16;
            const int col = cb + j * 8;
            if (EPI == 0) {
                float* p0 = C + (size_t)z * sC + (size_t)r0 * ldc + col;
                *(float2*)p0 = make_float2(a4[0], a4[1]);
                *(float2*)(p0 + 8 * (size_t)ldc) = make_float2(a4[2], a4[3]);
            } else if (EPI == 2) {
                float2 bv = *(const float2*)(bias + col);
                float* p0 = C + (size_t)r0 * ldc + col;
                *(float2*)p0 = make_float2(tanhf(a4[0] + bv.x), tanhf(a4[1] + bv.y));
                *(float2*)(p0 + 8 * (size_t)ldc) =
                    make_float2(tanhf(a4[2] + bv.x), tanhf(a4[3] + bv.y));
            } else {
                bf16 h0, l0, h1, l1;
                size_t off = (size_t)z * sC + (size_t)r0 * ldc + col;
                split1(a4[0], h0, l0); split1(a4[1], h1, l1);
                *(uint32_t*)(Ch + off) = pkbf(h0, h1);
                *(uint32_t*)(Cl + off) = pkbf(l0, l1);
                split1(a4[2], h0, l0); split1(a4[3], h1, l1);
                *(uint32_t*)(Ch + off + 8 * (size_t)ldc) = pkbf(h0, h1);
                *(uint32_t*)(Cl + off + 8 * (size_t)ldc) = pkbf(l0, l1);
            }
        }
    }
}

// ---------------------------------------------------------------------------
// fp32 -> (hi, lo) bf16 split, vectorized
// ---------------------------------------------------------------------------
__global__ void convert_split(const float4* __restrict__ in, uint2* __restrict__ hi,
                              uint2* __restrict__ lo, int n4)
{
    int i = blockIdx.x * blockDim.x + threadIdx.x;
    if (i >= n4) return;
    float4 v = in[i];
    bf16 h0, l0, h1, l1, h2, l2, h3, l3;
    split1(v.x, h0, l0); split1(v.y, h1, l1);
    split1(v.z, h2, l2); split1(v.w, h3, l3);
    hi[i] = make_uint2(pkbf(h0, h1), pkbf(h2, h3));
    lo[i] = make_uint2(pkbf(l0, l1), pkbf(l2, l3));
}

// ---------------------------------------------------------------------------
// enc [b,s,h] fp32 -> encT hi/lo bf16 [b,h,s]
// ---------------------------------------------------------------------------
__global__ void transpose_split(const float* __restrict__ enc,
                                bf16* __restrict__ Th, bf16* __restrict__ Tl)
{
    __shared__ float tile[32][33];
    const int b = blockIdx.z;
    const int s0 = blockIdx.y * 32;
    const int h0 = blockIdx.x * 32;
    const int tx = threadIdx.x & 31;
    const int ty = threadIdx.x >> 5;   // 0..7

    const float* src = enc + (size_t)b * Ss * Hh;
#pragma unroll
    for (int i = 0; i < 4; i++)
        tile[ty + i * 8][tx] = src[(size_t)(s0 + ty + i * 8) * Hh + h0 + tx];
    __syncthreads();

#pragma unroll
    for (int i = 0; i < 4; i++) {
        int hr = ty + i * 8;
        float v = tile[tx][hr];
        bf16 h, l;
        split1(v, h, l);
        size_t off = (size_t)b * Hh * Ss + (size_t)(h0 + hr) * Ss + s0 + tx;
        Th[off] = h;
        Tl[off] = l;
    }
}

// ---------------------------------------------------------------------------
// Row softmax (in place, fp32) + split-bf16 P output
// ---------------------------------------------------------------------------
__global__ void softmax_split(float* __restrict__ attn,
                              bf16* __restrict__ Ph, bf16* __restrict__ Pl)
{
    __shared__ float red[8];
    const size_t base = (size_t)blockIdx.x * Ss;
    float* p = attn + base;
    const int tid = threadIdx.x;

    float4 v0 = *(const float4*)(p + tid * 8);
    float4 v1 = *(const float4*)(p + tid * 8 + 4);

    float m = fmaxf(fmaxf(fmaxf(v0.x, v0.y), fmaxf(v0.z, v0.w)),
                    fmaxf(fmaxf(v1.x, v1.y), fmaxf(v1.z, v1.w)));
#pragma unroll
    for (int o = 16; o > 0; o >>= 1) m = fmaxf(m, __shfl_xor_sync(0xffffffffu, m, o));
    if ((tid & 31) == 0) red[tid >> 5] = m;
    __syncthreads();
    float mm = red[0];
#pragma unroll
    for (int i = 1; i < 8; i++) mm = fmaxf(mm, red[i]);
    __syncthreads();

    v0.x = __expf(v0.x - mm); v0.y = __expf(v0.y - mm);
    v0.z = __expf(v0.z - mm); v0.w = __expf(v0.w - mm);
    v1.x = __expf(v1.x - mm); v1.y = __expf(v1.y - mm);
    v1.z = __expf(v1.z - mm); v1.w = __expf(v1.w - mm);

    float s = v0.x + v0.y + v0.z + v0.w + v1.x + v1.y + v1.z + v1.w;
#pragma unroll
    for (int o = 16; o > 0; o >>= 1) s += __shfl_xor_sync(0xffffffffu, s, o);
    if ((tid & 31) == 0) red[tid >> 5] = s;
    __syncthreads();
    float ss = 0.f;
#pragma unroll
    for (int i = 0; i < 8; i++) ss += red[i];
    float inv = 1.0f / ss;

    v0.x *= inv; v0.y *= inv; v0.z *= inv; v0.w *= inv;
    v1.x *= inv; v1.y *= inv; v1.z *= inv; v1.w *= inv;
    *(float4*)(p + tid * 8) = v0;
    *(float4*)(p + tid * 8 + 4) = v1;

    float vv[8] = {v0.x, v0.y, v0.z, v0.w, v1.x, v1.y, v1.z, v1.w};
    uint32_t hp[4], lp[4];
#pragma unroll
    for (int j = 0; j < 4; j++) {
        bf16 h0, l0, h1, l1;
        split1(vv[2 * j], h0, l0);
        split1(vv[2 * j + 1], h1, l1);
        hp[j] = pkbf(h0, h1);
        lp[j] = pkbf(l0, l1);
    }
    *(uint4*)(Ph + base + tid * 8) = *(uint4*)hp;
    *(uint4*)(Pl + base + tid * 8) = *(uint4*)lp;
}

// ---------------------------------------------------------------------------
// Launch
// ---------------------------------------------------------------------------
extern "C" void kernel_launch(void* const* d_in, const int* in_sizes, int n_in,
                              void* d_out, int out_size)
{
    const float* enc  = (const float*)d_in[0];
    const float* dec  = (const float*)d_in[1];
    const float* W    = (const float*)d_in[2];
    const float* bias = (const float*)d_in[3];
    float* outp = (float*)d_out;

    const size_t OUT_N = (size_t)Bb * Tt * Hh;
    const size_t ATT_N = (size_t)Bb * Tt * Ss;

    bf16 *enc_hi, *enc_lo, *dec_hi, *dec_lo, *encT_hi, *encT_lo;
    bf16 *P_hi, *P_lo, *ctx_hi, *ctx_lo, *W_hi, *W_lo;
    cudaGetSymbolAddress((void**)&enc_hi, g_enc_hi);
    cudaGetSymbolAddress((void**)&enc_lo, g_enc_lo);
    cudaGetSymbolAddress((void**)&dec_hi, g_dec_hi);
    cudaGetSymbolAddress((void**)&dec_lo, g_dec_lo);
    cudaGetSymbolAddress((void**)&encT_hi, g_encT_hi);
    cudaGetSymbolAddress((void**)&encT_lo, g_encT_lo);
    cudaGetSymbolAddress((void**)&P_hi, g_P_hi);
    cudaGetSymbolAddress((void**)&P_lo, g_P_lo);
    cudaGetSymbolAddress((void**)&ctx_hi, g_ctx_hi);
    cudaGetSymbolAddress((void**)&ctx_lo, g_ctx_lo);
    cudaGetSymbolAddress((void**)&W_hi, g_W_hi);
    cudaGetSymbolAddress((void**)&W_lo, g_W_lo);

    float* attn;
    if ((size_t)out_size >= OUT_N + ATT_N) {
        attn = outp + OUT_N;
    } else {
        cudaGetSymbolAddress((void**)&attn, g_attn_fallback);
    }

    cudaFuncSetAttribute(gemm_mma<0>, cudaFuncAttributeMaxDynamicSharedMemorySize, SMEM_DYN);
    cudaFuncSetAttribute(gemm_mma<1>, cudaFuncAttributeMaxDynamicSharedMemorySize, SMEM_DYN);
    cudaFuncSetAttribute(gemm_mma<2>, cudaFuncAttributeMaxDynamicSharedMemorySize, SMEM_DYN);

    // 1) fp32 -> split bf16 conversions
    {
        int n4 = (int)((size_t)Bb * Ss * Hh / 4);
        convert_split<<<n4 / 256, 256>>>((const float4*)enc, (uint2*)enc_hi, (uint2*)enc_lo, n4);
        convert_split<<<n4 / 256, 256>>>((const float4*)dec, (uint2*)dec_hi, (uint2*)dec_lo, n4);
        int w4 = (int)((size_t)Hh * 2 * Hh / 4);
        convert_split<<<w4 / 256, 256>>>((const float4*)W, (uint2*)W_hi, (uint2*)W_lo, w4);
    }
    // 2) enc transpose+split for GEMM2's B
    transpose_split<<<dim3(Hh / 32, Ss / 32, Bb), 256>>>(enc, encT_hi, encT_lo);

    // 3) logits = dec . enc^T   (split: hh + lh + hl)
    {
        GemmArgs ga;
        ga.nseg = 3;
        long long sD = (long long)Tt * Hh, sE = (long long)Ss * Hh;
        ga.seg[0] = {dec_hi, enc_hi, Hh, Hh, Hh, sD, sE};
        ga.seg[1] = {dec_lo, enc_hi, Hh, Hh, Hh, sD, sE};
        ga.seg[2] = {dec_hi, enc_lo, Hh, Hh, Hh, sD, sE};
        gemm_mma<0><<<dim3(Ss / 128, Tt / 128, Bb), 128, SMEM_DYN>>>(
            ga, attn, nullptr, nullptr, nullptr, Ss, (long long)Tt * Ss);
    }

    // 4) softmax + P split
    softmax_split<<<Bb * Tt, 256>>>(attn, P_hi, P_lo);

    // 5) ctx = P . enc  (B = encT, k = s), epilogue writes ctx hi/lo
    {
        GemmArgs ga;
        ga.nseg = 3;
        long long sP = (long long)Tt * Ss, sT = (long long)Hh * Ss;
        ga.seg[0] = {P_hi, encT_hi, Ss, Ss, Ss, sP, sT};
        ga.seg[1] = {P_lo, encT_hi, Ss, Ss, Ss, sP, sT};
        ga.seg[2] = {P_hi, encT_lo, Ss, Ss, Ss, sP, sT};
        gemm_mma<1><<<dim3(Hh / 128, Tt / 128, Bb), 128, SMEM_DYN>>>(
            ga, nullptr, ctx_hi, ctx_lo, nullptr, Hh, (long long)Tt * Hh);
    }

    // 6) out = tanh([ctx|dec] . W^T + b); cat split over 6 segments
    {
        GemmArgs ga;
        ga.nseg = 6;
        const int ldw = 2 * Hh;
        ga.seg[0] = {ctx_hi, W_hi,        Hh, Hh, ldw, 0, 0};
        ga.seg[1] = {dec_hi, W_hi + Hh,   Hh, Hh, ldw, 0, 0};
        ga.seg[2] = {ctx_lo, W_hi,        Hh, Hh, ldw, 0, 0};
        ga.seg[3] = {dec_lo, W_hi + Hh,   Hh, Hh, ldw, 0, 0};
        ga.seg[4] = {ctx_hi, W_lo,        Hh, Hh, ldw, 0, 0};
        ga.seg[5] = {dec_hi, W_lo + Hh,   Hh, Hh, ldw, 0, 0};
        gemm_mma<2><<<dim3(Hh / 128, (Bb * Tt) / 128, 1), 128, SMEM_DYN>>>(
            ga, outp, nullptr, nullptr, bias, Hh, 0);
    }
}

// round 11
// speedup vs baseline: 2.7565x; 1.4597x over previous
#include <cuda_runtime.h>
#include <cuda_bf16.h>
#include <math.h>
#include <stdint.h>

#define Bb 16
#define Tt 2048
#define Ss 2048
#define Hh 1024

typedef __nv_bfloat16 bf16;
typedef unsigned long long ull;

// ---------------------------------------------------------------------------
// Device-global scratch (no runtime allocation allowed)
// ---------------------------------------------------------------------------
__device__ __align__(256) bf16 g_enc_hi[(size_t)Bb * Ss * Hh];
__device__ __align__(256) bf16 g_enc_lo[(size_t)Bb * Ss * Hh];
__device__ __align__(256) bf16 g_dec_hi[(size_t)Bb * Tt * Hh];
__device__ __align__(256) bf16 g_dec_lo[(size_t)Bb * Tt * Hh];
__device__ __align__(256) bf16 g_ctx_hi[(size_t)Bb * Tt * Hh];
__device__ __align__(256) bf16 g_ctx_lo[(size_t)Bb * Tt * Hh];
__device__ __align__(256) bf16 g_W_hi[(size_t)Hh * 2 * Hh];
__device__ __align__(256) bf16 g_W_lo[(size_t)Hh * 2 * Hh];
__device__ __align__(16)  float g_attn_fallback[(size_t)Bb * Tt * Ss];

// ---------------------------------------------------------------------------
// PTX helpers (target-portable only: cp.async, ldmatrix, mma.sync)
// ---------------------------------------------------------------------------
__device__ __forceinline__ uint32_t cvta_s(const void* p) {
    uint32_t a;
    asm("{ .reg .u64 t; cvta.to.shared.u64 t, %1; cvt.u32.u64 %0, t; }"
        : "=r"(a) : "l"(p));
    return a;
}
__device__ __forceinline__ void cp16(uint32_t saddr, const void* gptr) {
    asm volatile("cp.async.cg.shared.global [%0], [%1], 16;"
                 :: "r"(saddr), "l"(__cvta_generic_to_global(gptr)));
}
__device__ __forceinline__ void cp_commit() {
    asm volatile("cp.async.commit_group;" ::: "memory");
}
template <int N>
__device__ __forceinline__ void cp_wait() {
    asm volatile("cp.async.wait_group %0;" :: "n"(N) : "memory");
}
__device__ __forceinline__ void ldsm4(uint32_t& r0, uint32_t& r1, uint32_t& r2,
                                      uint32_t& r3, uint32_t addr) {
    asm volatile("ldmatrix.sync.aligned.m8n8.x4.shared.b16 {%0,%1,%2,%3}, [%4];"
                 : "=r"(r0), "=r"(r1), "=r"(r2), "=r"(r3) : "r"(addr));
}
__device__ __forceinline__ void mma_bf16(float* c, const uint32_t* a,
                                         uint32_t b0, uint32_t b1) {
    asm volatile(
        "mma.sync.aligned.m16n8k16.row.col.f32.bf16.bf16.f32 "
        "{%0,%1,%2,%3}, {%4,%5,%6,%7}, {%8,%9}, {%0,%1,%2,%3};"
        : "+f"(c[0]), "+f"(c[1]), "+f"(c[2]), "+f"(c[3])
        : "r"(a[0]), "r"(a[1]), "r"(a[2]), "r"(a[3]), "r"(b0), "r"(b1));
}
__device__ __forceinline__ void split1(float x, bf16& h, bf16& l) {
    h = __float2bfloat16(x);
    l = __float2bfloat16(x - __bfloat162float(h));
}
__device__ __forceinline__ uint32_t pkbf(bf16 a, bf16 b) {
    __nv_bfloat162 t(a, b);
    return *reinterpret_cast<uint32_t*>(&t);
}

// ---------------------------------------------------------------------------
// Generic segmented split-bf16 MMA GEMM: D[m,n] = sum_seg A_s[m,:].B_s[n,:]
// CTA tile 128x128, 128 thr (4 warps 2x2, warp tile 64x64), K-chunks of 32,
// padded SMEM (stride 40 halves), 4-stage cp.async pipeline, ldmatrix+mma.sync.
// ---------------------------------------------------------------------------
struct Seg {
    const bf16* A; const bf16* B;
    int K; int lda; int ldb;
    long long sA; long long sB;   // batch strides (elements)
};
struct GemmArgs { Seg seg[6]; int nseg; };

#define KCH 32
#define SSTRIDE 80            // bytes per SMEM row (40 halves)
#define ABUF 10240            // 128 * 80
#define NSTAGE 4
#define SMEM_DYN (2 * NSTAGE * ABUF)   // 81920

__device__ __forceinline__ void load_chunk(uint32_t sA, uint32_t sB,
                                           const bf16* A, const bf16* Bm,
                                           int lda, int ldb, int tid) {
#pragma unroll
    for (int i = 0; i < 4; i++) {
        int lin = tid + (i << 7);
        int row = lin >> 2, seg = lin & 3;
        cp16(sA + row * SSTRIDE + seg * 16, A + (size_t)row * lda + seg * 8);
    }
#pragma unroll
    for (int i = 0; i < 4; i++) {
        int lin = tid + (i << 7);
        int row = lin >> 2, seg = lin & 3;
        cp16(sB + row * SSTRIDE + seg * 16, Bm + (size_t)row * ldb + seg * 8);
    }
}

// EPI: 0 = store fp32 C, 2 = tanh(v + bias) -> C
template <int EPI>
__global__ void __launch_bounds__(128, 2) gemm_mma(
    GemmArgs ga, float* __restrict__ C,
    const float* __restrict__ bias, int ldc, long long sC)
{
    extern __shared__ __align__(16) char smem[];
    const uint32_t sbase = cvta_s(smem);

    const int tid = threadIdx.x;
    const int lane = tid & 31;
    const int wid = tid >> 5;           // 0..3
    const int wm = (wid >> 1) * 64;     // warp row offset  (0 / 64)
    const int wn = (wid & 1) * 64;      // warp col offset  (0 / 64)
    const int z = blockIdx.z;
    const int m0 = blockIdx.y * 128;
    const int n0 = blockIdx.x * 128;

    float acc[4][8][4];                 // [m16-subtile][n8-subtile][frag]
#pragma unroll
    for (int i = 0; i < 4; i++)
#pragma unroll
        for (int j = 0; j < 8; j++)
#pragma unroll
            for (int t = 0; t < 4; t++) acc[i][j][t] = 0.f;

    int total = 0;
#pragma unroll
    for (int i = 0; i < 6; i++)
        if (i < ga.nseg) total += ga.seg[i].K / KCH;

    // ldmatrix lane addressing (within warp tile)
    const int lrow = lane & 15;         // row within 16-row subtile
    const int lcol = (lane >> 4) * 16;  // 16B column selector

    // load cursor
    int lsi = 0, lko = 0;
    // Prologue: prefetch chunks 0..2 into stages 0..2
#pragma unroll
    for (int pf = 0; pf < NSTAGE - 1; pf++) {
        if (pf < total) {
            const Seg& sg = ga.seg[lsi];
            load_chunk(sbase + pf * ABUF, sbase + (NSTAGE + pf) * ABUF,
                       sg.A + z * sg.sA + (size_t)m0 * sg.lda + lko,
                       sg.B + z * sg.sB + (size_t)n0 * sg.ldb + lko,
                       sg.lda, sg.ldb, tid);
            cp_commit();
            lko += KCH;
            if (lko >= ga.seg[lsi].K) { lko = 0; lsi++; }
        }
    }

    for (int gc = 0; gc < total; gc++) {
        const int st = gc & (NSTAGE - 1);
        // chunk gc must have landed; allow the newest in-flight chunks to fly
        if (gc + 2 < total)      cp_wait<2>();
        else if (gc + 1 < total) cp_wait<1>();
        else                     cp_wait<0>();
        __syncthreads();   // data visible + all warps done with the slot reused below

        if (gc + NSTAGE - 1 < total) {
            const int ls = (gc + NSTAGE - 1) & (NSTAGE - 1);
            const Seg& sg = ga.seg[lsi];
            load_chunk(sbase + ls * ABUF, sbase + (NSTAGE + ls) * ABUF,
                       sg.A + z * sg.sA + (size_t)m0 * sg.lda + lko,
                       sg.B + z * sg.sB + (size_t)n0 * sg.ldb + lko,
                       sg.lda, sg.ldb, tid);
            cp_commit();
            lko += KCH;
            if (lko >= ga.seg[lsi].K) { lko = 0; lsi++; }
        }

        const uint32_t aB = sbase + st * ABUF;
        const uint32_t bB = sbase + (NSTAGE + st) * ABUF;
#pragma unroll
        for (int ko = 0; ko < 2; ko++) {                 // two k16 steps
            const uint32_t kb = ko * 32 + lcol;
            uint32_t af[4][4];
#pragma unroll
            for (int mi = 0; mi < 4; mi++) {
                uint32_t addr = aB + (uint32_t)(wm + mi * 16 + lrow) * SSTRIDE + kb;
                ldsm4(af[mi][0], af[mi][1], af[mi][2], af[mi][3], addr);
            }
            uint32_t bf_[4][4];
#pragma unroll
            for (int bi = 0; bi < 4; bi++) {
                uint32_t addr = bB + (uint32_t)(wn + bi * 16 + lrow) * SSTRIDE + kb;
                ldsm4(bf_[bi][0], bf_[bi][1], bf_[bi][2], bf_[bi][3], addr);
            }
#pragma unroll
            for (int mi = 0; mi < 4; mi++)
#pragma unroll
                for (int j = 0; j < 8; j++) {
                    const int bi = j >> 1, hi = j & 1;
                    mma_bf16(acc[mi][j], af[mi], bf_[bi][hi], bf_[bi][hi + 2]);
                }
        }
    }

    // Epilogue: thread (mi,j) owns rows r0,r0+8 and cols col,col+1
    const int rb = m0 + wm + (lane >> 2);
    const int cb = n0 + wn + (lane & 3) * 2;
#pragma unroll
    for (int mi = 0; mi < 4; mi++) {
#pragma unroll
        for (int j = 0; j < 8; j++) {
            const float* a4 = acc[mi][j];
            const int r0 = rb + mi * 16;
            const int col = cb + j * 8;
            if (EPI == 0) {
                float* p0 = C + (size_t)z * sC + (size_t)r0 * ldc + col;
                *(float2*)p0 = make_float2(a4[0], a4[1]);
                *(float2*)(p0 + 8 * (size_t)ldc) = make_float2(a4[2], a4[3]);
            } else {
                float2 bv = *(const float2*)(bias + col);
                float* p0 = C + (size_t)r0 * ldc + col;
                *(float2*)p0 = make_float2(tanhf(a4[0] + bv.x), tanhf(a4[1] + bv.y));
                *(float2*)(p0 + 8 * (size_t)ldc) =
                    make_float2(tanhf(a4[2] + bv.x), tanhf(a4[3] + bv.y));
            }
        }
    }
}

// ---------------------------------------------------------------------------
// fp32 -> (hi, lo) bf16 split, vectorized
// ---------------------------------------------------------------------------
__global__ void convert_split(const float4* __restrict__ in, uint2* __restrict__ hi,
                              uint2* __restrict__ lo, int n4)
{
    int i = blockIdx.x * blockDim.x + threadIdx.x;
    if (i >= n4) return;
    float4 v = in[i];
    bf16 h0, l0, h1, l1, h2, l2, h3, l3;
    split1(v.x, h0, l0); split1(v.y, h1, l1);
    split1(v.z, h2, l2); split1(v.w, h3, l3);
    hi[i] = make_uint2(pkbf(h0, h1), pkbf(h2, h3));
    lo[i] = make_uint2(pkbf(l0, l1), pkbf(l2, l3));
}

// ---------------------------------------------------------------------------
// Row softmax over attn[b,t,:] (rows of length Ss=2048), in place.
// ---------------------------------------------------------------------------
__global__ void softmax_kernel(float* __restrict__ attn)
{
    __shared__ float red[8];
    float* p = attn + (size_t)blockIdx.x * Ss;
    const int tid = threadIdx.x;

    float4 v0 = *(const float4*)(p + tid * 8);
    float4 v1 = *(const float4*)(p + tid * 8 + 4);

    float m = fmaxf(fmaxf(fmaxf(v0.x, v0.y), fmaxf(v0.z, v0.w)),
                    fmaxf(fmaxf(v1.x, v1.y), fmaxf(v1.z, v1.w)));
#pragma unroll
    for (int o = 16; o > 0; o >>= 1) m = fmaxf(m, __shfl_xor_sync(0xffffffffu, m, o));
    if ((tid & 31) == 0) red[tid >> 5] = m;
    __syncthreads();
    float mm = red[0];
#pragma unroll
    for (int i = 1; i < 8; i++) mm = fmaxf(mm, red[i]);
    __syncthreads();

    v0.x = __expf(v0.x - mm); v0.y = __expf(v0.y - mm);
    v0.z = __expf(v0.z - mm); v0.w = __expf(v0.w - mm);
    v1.x = __expf(v1.x - mm); v1.y = __expf(v1.y - mm);
    v1.z = __expf(v1.z - mm); v1.w = __expf(v1.w - mm);

    float s = v0.x + v0.y + v0.z + v0.w + v1.x + v1.y + v1.z + v1.w;
#pragma unroll
    for (int o = 16; o > 0; o >>= 1) s += __shfl_xor_sync(0xffffffffu, s, o);
    if ((tid & 31) == 0) red[tid >> 5] = s;
    __syncthreads();
    float ss = 0.f;
#pragma unroll
    for (int i = 0; i < 8; i++) ss += red[i];
    float inv = 1.0f / ss;

    v0.x *= inv; v0.y *= inv; v0.z *= inv; v0.w *= inv;
    v1.x *= inv; v1.y *= inv; v1.z *= inv; v1.w *= inv;
    *(float4*)(p + tid * 8) = v0;
    *(float4*)(p + tid * 8 + 4) = v1;
}

// ---------------------------------------------------------------------------
// Sparse ctx: ctx[row,:] = sum_{s: p[row,s] > TAU} p[row,s] * enc[b,s,:]
// One block per row, 256 threads. Deterministic order-preserving compaction
// (per-thread contiguous ranges + block exclusive scan), fp32 accumulation,
// split-bf16 store. Exact up to dropped mass <= 2048*TAU (rel ~1e-5).
// ---------------------------------------------------------------------------
#define TAU 1e-7f
__global__ void __launch_bounds__(256) sparse_ctx(
    const float* __restrict__ attn, const float* __restrict__ enc,
    bf16* __restrict__ Ch, bf16* __restrict__ Cl)
{
    __shared__ int   s_idx[Ss];
    __shared__ float s_p[Ss];
    __shared__ int   s_cnt[256];

    const int row = blockIdx.x;           // 0 .. Bb*Tt-1
    const int b = row >> 11;              // row / Tt
    const int tid = threadIdx.x;
    const float* p = attn + (size_t)row * Ss;

    // Phase 1: deterministic compaction of survivors (sorted by s)
    float pv[8];
    *(float4*)(pv)     = *(const float4*)(p + tid * 8);
    *(float4*)(pv + 4) = *(const float4*)(p + tid * 8 + 4);
    int cnt = 0;
#pragma unroll
    for (int i = 0; i < 8; i++) cnt += (pv[i] > TAU) ? 1 : 0;

    s_cnt[tid] = cnt;
    __syncthreads();
    // Hillis-Steele inclusive scan (read-all-then-write, sync-separated)
    for (int off = 1; off < 256; off <<= 1) {
        int v = s_cnt[tid];
        int add = (tid >= off) ? s_cnt[tid - off] : 0;
        __syncthreads();
        s_cnt[tid] = v + add;
        __syncthreads();
    }
    int wr = s_cnt[tid] - cnt;
    const int total = s_cnt[255];
#pragma unroll
    for (int i = 0; i < 8; i++) {
        if (pv[i] > TAU) { s_idx[wr] = tid * 8 + i; s_p[wr] = pv[i]; wr++; }
    }
    __syncthreads();

    // Phase 2: accumulate; thread owns columns [tid*4, tid*4+4)
    float4 acc = make_float4(0.f, 0.f, 0.f, 0.f);
    const float* eb = enc + (size_t)b * Ss * Hh;
    for (int i = 0; i < total; i++) {
        const float w = s_p[i];
        const float4 e = *(const float4*)(eb + (size_t)s_idx[i] * Hh + tid * 4);
        acc.x += w * e.x; acc.y += w * e.y; acc.z += w * e.z; acc.w += w * e.w;
    }

    // Split-bf16 store
    bf16 h0, l0, h1, l1, h2, l2, h3, l3;
    split1(acc.x, h0, l0); split1(acc.y, h1, l1);
    split1(acc.z, h2, l2); split1(acc.w, h3, l3);
    const size_t off = (size_t)row * Hh + tid * 4;
    *(uint2*)(Ch + off) = make_uint2(pkbf(h0, h1), pkbf(h2, h3));
    *(uint2*)(Cl + off) = make_uint2(pkbf(l0, l1), pkbf(l2, l3));
}

// ---------------------------------------------------------------------------
// Launch
// ---------------------------------------------------------------------------
extern "C" void kernel_launch(void* const* d_in, const int* in_sizes, int n_in,
                              void* d_out, int out_size)
{
    const float* enc  = (const float*)d_in[0];
    const float* dec  = (const float*)d_in[1];
    const float* W    = (const float*)d_in[2];
    const float* bias = (const float*)d_in[3];
    float* outp = (float*)d_out;

    const size_t OUT_N = (size_t)Bb * Tt * Hh;
    const size_t ATT_N = (size_t)Bb * Tt * Ss;

    bf16 *enc_hi, *enc_lo, *dec_hi, *dec_lo, *ctx_hi, *ctx_lo, *W_hi, *W_lo;
    cudaGetSymbolAddress((void**)&enc_hi, g_enc_hi);
    cudaGetSymbolAddress((void**)&enc_lo, g_enc_lo);
    cudaGetSymbolAddress((void**)&dec_hi, g_dec_hi);
    cudaGetSymbolAddress((void**)&dec_lo, g_dec_lo);
    cudaGetSymbolAddress((void**)&ctx_hi, g_ctx_hi);
    cudaGetSymbolAddress((void**)&ctx_lo, g_ctx_lo);
    cudaGetSymbolAddress((void**)&W_hi, g_W_hi);
    cudaGetSymbolAddress((void**)&W_lo, g_W_lo);

    float* attn;
    if ((size_t)out_size >= OUT_N + ATT_N) {
        attn = outp + OUT_N;
    } else {
        cudaGetSymbolAddress((void**)&attn, g_attn_fallback);
    }

    cudaFuncSetAttribute(gemm_mma<0>, cudaFuncAttributeMaxDynamicSharedMemorySize, SMEM_DYN);
    cudaFuncSetAttribute(gemm_mma<2>, cudaFuncAttributeMaxDynamicSharedMemorySize, SMEM_DYN);

    // 1) fp32 -> split bf16 conversions
    {
        int n4 = (int)((size_t)Bb * Ss * Hh / 4);
        convert_split<<<n4 / 256, 256>>>((const float4*)enc, (uint2*)enc_hi, (uint2*)enc_lo, n4);
        convert_split<<<n4 / 256, 256>>>((const float4*)dec, (uint2*)dec_hi, (uint2*)dec_lo, n4);
        int w4 = (int)((size_t)Hh * 2 * Hh / 4);
        convert_split<<<w4 / 256, 256>>>((const float4*)W, (uint2*)W_hi, (uint2*)W_lo, w4);
    }

    // 2) logits = dec . enc^T   (split: hh + lh + hl)
    {
        GemmArgs ga;
        ga.nseg = 3;
        long long sD = (long long)Tt * Hh, sE = (long long)Ss * Hh;
        ga.seg[0] = {dec_hi, enc_hi, Hh, Hh, Hh, sD, sE};
        ga.seg[1] = {dec_lo, enc_hi, Hh, Hh, Hh, sD, sE};
        ga.seg[2] = {dec_hi, enc_lo, Hh, Hh, Hh, sD, sE};
        gemm_mma<0><<<dim3(Ss / 128, Tt / 128, Bb), 128, SMEM_DYN>>>(
            ga, attn, nullptr, Ss, (long long)Tt * Ss);
    }

    // 3) softmax rows, in place
    softmax_kernel<<<Bb * Tt, 256>>>(attn);

    // 4) ctx = P . enc as sparse gather (P near-one-hot), split-bf16 output
    sparse_ctx<<<Bb * Tt, 256>>>(attn, enc, ctx_hi, ctx_lo);

    // 5) out = tanh([ctx|dec] . W^T + b); cat split over 6 segments
    {
        GemmArgs ga;
        ga.nseg = 6;
        const int ldw = 2 * Hh;
        ga.seg[0] = {ctx_hi, W_hi,        Hh, Hh, ldw, 0, 0};
        ga.seg[1] = {dec_hi, W_hi + Hh,   Hh, Hh, ldw, 0, 0};
        ga.seg[2] = {ctx_lo, W_hi,        Hh, Hh, ldw, 0, 0};
        ga.seg[3] = {dec_lo, W_hi + Hh,   Hh, Hh, ldw, 0, 0};
        ga.seg[4] = {ctx_hi, W_lo,        Hh, Hh, ldw, 0, 0};
        ga.seg[5] = {dec_hi, W_lo + Hh,   Hh, Hh, ldw, 0, 0};
        gemm_mma<2><<<dim3(Hh / 128, (Bb * Tt) / 128, 1), 128, SMEM_DYN>>>(
            ga, outp, bias, Hh, 0);
    }
}

// round 13
// speedup vs baseline: 3.5889x; 1.3020x over previous
#include <cuda_runtime.h>
#include <cuda_bf16.h>
#include <math.h>
#include <stdint.h>

#define Bb 16
#define Tt 2048
#define Ss 2048
#define Hh 1024

typedef __nv_bfloat16 bf16;
typedef unsigned long long ull;

// ---------------------------------------------------------------------------
// Device-global scratch (no runtime allocation allowed)
// ---------------------------------------------------------------------------
__device__ __align__(256) bf16 g_enc_hi[(size_t)Bb * Ss * Hh];
__device__ __align__(256) bf16 g_enc_lo[(size_t)Bb * Ss * Hh];
__device__ __align__(256) bf16 g_dec_hi[(size_t)Bb * Tt * Hh];
__device__ __align__(256) bf16 g_dec_lo[(size_t)Bb * Tt * Hh];
__device__ __align__(256) bf16 g_ctx_hi[(size_t)Bb * Tt * Hh];
__device__ __align__(256) bf16 g_ctx_lo[(size_t)Bb * Tt * Hh];
__device__ __align__(256) bf16 g_W_hi[(size_t)Hh * 2 * Hh];
__device__ __align__(256) bf16 g_W_lo[(size_t)Hh * 2 * Hh];
__device__ __align__(16)  float g_attn_fallback[(size_t)Bb * Tt * Ss];

// ---------------------------------------------------------------------------
// PTX helpers (target-portable only: cp.async, ldmatrix, mma.sync)
// ---------------------------------------------------------------------------
__device__ __forceinline__ uint32_t cvta_s(const void* p) {
    uint32_t a;
    asm("{ .reg .u64 t; cvta.to.shared.u64 t, %1; cvt.u32.u64 %0, t; }"
        : "=r"(a) : "l"(p));
    return a;
}
__device__ __forceinline__ void cp16(uint32_t saddr, const void* gptr) {
    asm volatile("cp.async.cg.shared.global [%0], [%1], 16;"
                 :: "r"(saddr), "l"(__cvta_generic_to_global(gptr)));
}
__device__ __forceinline__ void cp_commit() {
    asm volatile("cp.async.commit_group;" ::: "memory");
}
template <int N>
__device__ __forceinline__ void cp_wait() {
    asm volatile("cp.async.wait_group %0;" :: "n"(N) : "memory");
}
__device__ __forceinline__ void ldsm4(uint32_t& r0, uint32_t& r1, uint32_t& r2,
                                      uint32_t& r3, uint32_t addr) {
    asm volatile("ldmatrix.sync.aligned.m8n8.x4.shared.b16 {%0,%1,%2,%3}, [%4];"
                 : "=r"(r0), "=r"(r1), "=r"(r2), "=r"(r3) : "r"(addr));
}
__device__ __forceinline__ void mma_bf16(float* c, const uint32_t* a,
                                         uint32_t b0, uint32_t b1) {
    asm volatile(
        "mma.sync.aligned.m16n8k16.row.col.f32.bf16.bf16.f32 "
        "{%0,%1,%2,%3}, {%4,%5,%6,%7}, {%8,%9}, {%0,%1,%2,%3};"
        : "+f"(c[0]), "+f"(c[1]), "+f"(c[2]), "+f"(c[3])
        : "r"(a[0]), "r"(a[1]), "r"(a[2]), "r"(a[3]), "r"(b0), "r"(b1));
}
__device__ __forceinline__ void split1(float x, bf16& h, bf16& l) {
    h = __float2bfloat16(x);
    l = __float2bfloat16(x - __bfloat162float(h));
}
__device__ __forceinline__ uint32_t pkbf(bf16 a, bf16 b) {
    __nv_bfloat162 t(a, b);
    return *reinterpret_cast<uint32_t*>(&t);
}

// ---------------------------------------------------------------------------
// Generic segmented split-bf16 MMA GEMM (unchanged from R10 winner)
// ---------------------------------------------------------------------------
struct Seg {
    const bf16* A; const bf16* B;
    int K; int lda; int ldb;
    long long sA; long long sB;
};
struct GemmArgs { Seg seg[6]; int nseg; };

#define KCH 32
#define SSTRIDE 80
#define ABUF 10240
#define NSTAGE 4
#define SMEM_DYN (2 * NSTAGE * ABUF)

__device__ __forceinline__ void load_chunk(uint32_t sA, uint32_t sB,
                                           const bf16* A, const bf16* Bm,
                                           int lda, int ldb, int tid) {
#pragma unroll
    for (int i = 0; i < 4; i++) {
        int lin = tid + (i << 7);
        int row = lin >> 2, seg = lin & 3;
        cp16(sA + row * SSTRIDE + seg * 16, A + (size_t)row * lda + seg * 8);
    }
#pragma unroll
    for (int i = 0; i < 4; i++) {
        int lin = tid + (i << 7);
        int row = lin >> 2, seg = lin & 3;
        cp16(sB + row * SSTRIDE + seg * 16, Bm + (size_t)row * ldb + seg * 8);
    }
}

// EPI: 0 = store fp32 C, 2 = tanh(v + bias) -> C
template <int EPI>
__global__ void __launch_bounds__(128, 2) gemm_mma(
    GemmArgs ga, float* __restrict__ C,
    const float* __restrict__ bias, int ldc, long long sC)
{
    extern __shared__ __align__(16) char smem[];
    const uint32_t sbase = cvta_s(smem);

    const int tid = threadIdx.x;
    const int lane = tid & 31;
    const int wid = tid >> 5;
    const int wm = (wid >> 1) * 64;
    const int wn = (wid & 1) * 64;
    const int z = blockIdx.z;
    const int m0 = blockIdx.y * 128;
    const int n0 = blockIdx.x * 128;

    float acc[4][8][4];
#pragma unroll
    for (int i = 0; i < 4; i++)
#pragma unroll
        for (int j = 0; j < 8; j++)
#pragma unroll
            for (int t = 0; t < 4; t++) acc[i][j][t] = 0.f;

    int total = 0;
#pragma unroll
    for (int i = 0; i < 6; i++)
        if (i < ga.nseg) total += ga.seg[i].K / KCH;

    const int lrow = lane & 15;
    const int lcol = (lane >> 4) * 16;

    int lsi = 0, lko = 0;
#pragma unroll
    for (int pf = 0; pf < NSTAGE - 1; pf++) {
        if (pf < total) {
            const Seg& sg = ga.seg[lsi];
            load_chunk(sbase + pf * ABUF, sbase + (NSTAGE + pf) * ABUF,
                       sg.A + z * sg.sA + (size_t)m0 * sg.lda + lko,
                       sg.B + z * sg.sB + (size_t)n0 * sg.ldb + lko,
                       sg.lda, sg.ldb, tid);
            cp_commit();
            lko += KCH;
            if (lko >= ga.seg[lsi].K) { lko = 0; lsi++; }
        }
    }

    for (int gc = 0; gc < total; gc++) {
        const int st = gc & (NSTAGE - 1);
        if (gc + 2 < total)      cp_wait<2>();
        else if (gc + 1 < total) cp_wait<1>();
        else                     cp_wait<0>();
        __syncthreads();

        if (gc + NSTAGE - 1 < total) {
            const int ls = (gc + NSTAGE - 1) & (NSTAGE - 1);
            const Seg& sg = ga.seg[lsi];
            load_chunk(sbase + ls * ABUF, sbase + (NSTAGE + ls) * ABUF,
                       sg.A + z * sg.sA + (size_t)m0 * sg.lda + lko,
                       sg.B + z * sg.sB + (size_t)n0 * sg.ldb + lko,
                       sg.lda, sg.ldb, tid);
            cp_commit();
            lko += KCH;
            if (lko >= ga.seg[lsi].K) { lko = 0; lsi++; }
        }

        const uint32_t aB = sbase + st * ABUF;
        const uint32_t bB = sbase + (NSTAGE + st) * ABUF;
#pragma unroll
        for (int ko = 0; ko < 2; ko++) {
            const uint32_t kb = ko * 32 + lcol;
            uint32_t af[4][4];
#pragma unroll
            for (int mi = 0; mi < 4; mi++) {
                uint32_t addr = aB + (uint32_t)(wm + mi * 16 + lrow) * SSTRIDE + kb;
                ldsm4(af[mi][0], af[mi][1], af[mi][2], af[mi][3], addr);
            }
            uint32_t bf_[4][4];
#pragma unroll
            for (int bi = 0; bi < 4; bi++) {
                uint32_t addr = bB + (uint32_t)(wn + bi * 16 + lrow) * SSTRIDE + kb;
                ldsm4(bf_[bi][0], bf_[bi][1], bf_[bi][2], bf_[bi][3], addr);
            }
#pragma unroll
            for (int mi = 0; mi < 4; mi++)
#pragma unroll
                for (int j = 0; j < 8; j++) {
                    const int bi = j >> 1, hi = j & 1;
                    mma_bf16(acc[mi][j], af[mi], bf_[bi][hi], bf_[bi][hi + 2]);
                }
        }
    }

    const int rb = m0 + wm + (lane >> 2);
    const int cb = n0 + wn + (lane & 3) * 2;
#pragma unroll
    for (int mi = 0; mi < 4; mi++) {
#pragma unroll
        for (int j = 0; j < 8; j++) {
            const float* a4 = acc[mi][j];
            const int r0 = rb + mi * 16;
            const int col = cb + j * 8;
            if (EPI == 0) {
                float* p0 = C + (size_t)z * sC + (size_t)r0 * ldc + col;
                *(float2*)p0 = make_float2(a4[0], a4[1]);
                *(float2*)(p0 + 8 * (size_t)ldc) = make_float2(a4[2], a4[3]);
            } else {
                float2 bv = *(const float2*)(bias + col);
                float* p0 = C + (size_t)r0 * ldc + col;
                *(float2*)p0 = make_float2(tanhf(a4[0] + bv.x), tanhf(a4[1] + bv.y));
                *(float2*)(p0 + 8 * (size_t)ldc) =
                    make_float2(tanhf(a4[2] + bv.x), tanhf(a4[3] + bv.y));
            }
        }
    }
}

// ---------------------------------------------------------------------------
// fp32 -> (hi, lo) bf16 split, vectorized
// ---------------------------------------------------------------------------
__global__ void convert_split(const float4* __restrict__ in, uint2* __restrict__ hi,
                              uint2* __restrict__ lo, int n4)
{
    int i = blockIdx.x * blockDim.x + threadIdx.x;
    if (i >= n4) return;
    float4 v = in[i];
    bf16 h0, l0, h1, l1, h2, l2, h3, l3;
    split1(v.x, h0, l0); split1(v.y, h1, l1);
    split1(v.z, h2, l2); split1(v.w, h3, l3);
    hi[i] = make_uint2(pkbf(h0, h1), pkbf(h2, h3));
    lo[i] = make_uint2(pkbf(l0, l1), pkbf(l2, l3));
}

// ---------------------------------------------------------------------------
// Refine + softmax: logits in attn are hh-only (bf16 error sigma~0.18).
// Per row: find approx max, compact candidates (logit > max-20), recompute
// those logits EXACTLY in fp32 (warp-per-candidate dot), patch, then softmax.
// Non-candidates have p < ~2e-9 relative to max: their logit error is
// irrelevant to attn global error and to the denominator (<1e-5 rel).
// ---------------------------------------------------------------------------
#define CAND_MAX 128
#define THRESH 20.0f

__global__ void __launch_bounds__(256) refine_softmax(
    float* __restrict__ attn, const float* __restrict__ enc,
    const float* __restrict__ dec)
{
    __shared__ float s_dec[Hh];
    __shared__ int   s_idx[CAND_MAX];
    __shared__ float s_exact[CAND_MAX];
    __shared__ int   s_cnt[256];
    __shared__ float red[8];

    const int row = blockIdx.x;
    const int b = row >> 11;
    const int t = row & 2047;
    const int tid = threadIdx.x;
    const int lane = tid & 31;
    const int wid = tid >> 5;
    float* p = attn + (size_t)row * Ss;

    // dec row -> smem
    {
        const float4 dv = *(const float4*)(dec + ((size_t)b * Tt + t) * Hh + tid * 4);
        *(float4*)&s_dec[tid * 4] = dv;
    }

    float pv[8];
    *(float4*)(pv)     = *(const float4*)(p + tid * 8);
    *(float4*)(pv + 4) = *(const float4*)(p + tid * 8 + 4);

    // approx row max
    float m = pv[0];
#pragma unroll
    for (int i = 1; i < 8; i++) m = fmaxf(m, pv[i]);
#pragma unroll
    for (int o = 16; o > 0; o >>= 1) m = fmaxf(m, __shfl_xor_sync(0xffffffffu, m, o));
    if (lane == 0) red[wid] = m;
    __syncthreads();
    float mm = red[0];
#pragma unroll
    for (int i = 1; i < 8; i++) mm = fmaxf(mm, red[i]);

    // candidate compaction (order-preserving)
    const float thr = mm - THRESH;
    int cnt = 0;
#pragma unroll
    for (int i = 0; i < 8; i++) cnt += (pv[i] > thr) ? 1 : 0;
    s_cnt[tid] = cnt;
    __syncthreads();
    for (int off = 1; off < 256; off <<= 1) {
        int v = s_cnt[tid];
        int add = (tid >= off) ? s_cnt[tid - off] : 0;
        __syncthreads();
        s_cnt[tid] = v + add;
        __syncthreads();
    }
    const int total0 = s_cnt[255];
    const int total = (total0 < CAND_MAX) ? total0 : CAND_MAX;
    {
        int wr = s_cnt[tid] - cnt;
#pragma unroll
        for (int i = 0; i < 8; i++) {
            if (pv[i] > thr) {
                if (wr < CAND_MAX) s_idx[wr] = tid * 8 + i;
                wr++;
            }
        }
    }
    __syncthreads();

    // exact fp32 dots: one warp per candidate
    for (int c = wid; c < total; c += 8) {
        const float* er = enc + ((size_t)b * Ss + s_idx[c]) * Hh;
        float sum = 0.f;
#pragma unroll
        for (int k = 0; k < 8; k++) {
            const int e0 = (lane + k * 32) * 4;
            const float4 e = *(const float4*)(er + e0);
            const float4 d = *(const float4*)&s_dec[e0];
            sum += e.x * d.x + e.y * d.y + e.z * d.z + e.w * d.w;
        }
#pragma unroll
        for (int o = 16; o > 0; o >>= 1) sum += __shfl_xor_sync(0xffffffffu, sum, o);
        if (lane == 0) s_exact[c] = sum;
    }
    __syncthreads();

    // patch local copies with exact logits
    {
        int wr = s_cnt[tid] - cnt;
#pragma unroll
        for (int i = 0; i < 8; i++) {
            if (pv[i] > thr) {
                if (wr < total) pv[i] = s_exact[wr];
                wr++;
            }
        }
    }
    __syncthreads();

    // exact max over patched values
    float m2 = pv[0];
#pragma unroll
    for (int i = 1; i < 8; i++) m2 = fmaxf(m2, pv[i]);
#pragma unroll
    for (int o = 16; o > 0; o >>= 1) m2 = fmaxf(m2, __shfl_xor_sync(0xffffffffu, m2, o));
    if (lane == 0) red[wid] = m2;
    __syncthreads();
    float mx = red[0];
#pragma unroll
    for (int i = 1; i < 8; i++) mx = fmaxf(mx, red[i]);
    __syncthreads();

    // exp + sum
    float s = 0.f;
#pragma unroll
    for (int i = 0; i < 8; i++) { pv[i] = __expf(pv[i] - mx); s += pv[i]; }
#pragma unroll
    for (int o = 16; o > 0; o >>= 1) s += __shfl_xor_sync(0xffffffffu, s, o);
    if (lane == 0) red[wid] = s;
    __syncthreads();
    float ss = 0.f;
#pragma unroll
    for (int i = 0; i < 8; i++) ss += red[i];
    const float inv = 1.0f / ss;

#pragma unroll
    for (int i = 0; i < 8; i++) pv[i] *= inv;
    *(float4*)(p + tid * 8)     = *(float4*)(pv);
    *(float4*)(p + tid * 8 + 4) = *(float4*)(pv + 4);
}

// ---------------------------------------------------------------------------
// Sparse ctx: ctx[row,:] = sum_{s: p[row,s] > TAU} p[row,s] * enc[b,s,:]
// ---------------------------------------------------------------------------
#define TAU 1e-7f
__global__ void __launch_bounds__(256) sparse_ctx(
    const float* __restrict__ attn, const float* __restrict__ enc,
    bf16* __restrict__ Ch, bf16* __restrict__ Cl)
{
    __shared__ int   s_idx[Ss];
    __shared__ float s_p[Ss];
    __shared__ int   s_cnt[256];

    const int row = blockIdx.x;
    const int b = row >> 11;
    const int tid = threadIdx.x;
    const float* p = attn + (size_t)row * Ss;

    float pv[8];
    *(float4*)(pv)     = *(const float4*)(p + tid * 8);
    *(float4*)(pv + 4) = *(const float4*)(p + tid * 8 + 4);
    int cnt = 0;
#pragma unroll
    for (int i = 0; i < 8; i++) cnt += (pv[i] > TAU) ? 1 : 0;

    s_cnt[tid] = cnt;
    __syncthreads();
    for (int off = 1; off < 256; off <<= 1) {
        int v = s_cnt[tid];
        int add = (tid >= off) ? s_cnt[tid - off] : 0;
        __syncthreads();
        s_cnt[tid] = v + add;
        __syncthreads();
    }
    int wr = s_cnt[tid] - cnt;
    const int total = s_cnt[255];
#pragma unroll
    for (int i = 0; i < 8; i++) {
        if (pv[i] > TAU) { s_idx[wr] = tid * 8 + i; s_p[wr] = pv[i]; wr++; }
    }
    __syncthreads();

    float4 acc = make_float4(0.f, 0.f, 0.f, 0.f);
    const float* eb = enc + (size_t)b * Ss * Hh;
    for (int i = 0; i < total; i++) {
        const float w = s_p[i];
        const float4 e = *(const float4*)(eb + (size_t)s_idx[i] * Hh + tid * 4);
        acc.x += w * e.x; acc.y += w * e.y; acc.z += w * e.z; acc.w += w * e.w;
    }

    bf16 h0, l0, h1, l1, h2, l2, h3, l3;
    split1(acc.x, h0, l0); split1(acc.y, h1, l1);
    split1(acc.z, h2, l2); split1(acc.w, h3, l3);
    const size_t off = (size_t)row * Hh + tid * 4;
    *(uint2*)(Ch + off) = make_uint2(pkbf(h0, h1), pkbf(h2, h3));
    *(uint2*)(Cl + off) = make_uint2(pkbf(l0, l1), pkbf(l2, l3));
}

// ---------------------------------------------------------------------------
// Launch
// ---------------------------------------------------------------------------
extern "C" void kernel_launch(void* const* d_in, const int* in_sizes, int n_in,
                              void* d_out, int out_size)
{
    const float* enc  = (const float*)d_in[0];
    const float* dec  = (const float*)d_in[1];
    const float* W    = (const float*)d_in[2];
    const float* bias = (const float*)d_in[3];
    float* outp = (float*)d_out;

    const size_t OUT_N = (size_t)Bb * Tt * Hh;
    const size_t ATT_N = (size_t)Bb * Tt * Ss;

    bf16 *enc_hi, *enc_lo, *dec_hi, *dec_lo, *ctx_hi, *ctx_lo, *W_hi, *W_lo;
    cudaGetSymbolAddress((void**)&enc_hi, g_enc_hi);
    cudaGetSymbolAddress((void**)&enc_lo, g_enc_lo);
    cudaGetSymbolAddress((void**)&dec_hi, g_dec_hi);
    cudaGetSymbolAddress((void**)&dec_lo, g_dec_lo);
    cudaGetSymbolAddress((void**)&ctx_hi, g_ctx_hi);
    cudaGetSymbolAddress((void**)&ctx_lo, g_ctx_lo);
    cudaGetSymbolAddress((void**)&W_hi, g_W_hi);
    cudaGetSymbolAddress((void**)&W_lo, g_W_lo);

    float* attn;
    if ((size_t)out_size >= OUT_N + ATT_N) {
        attn = outp + OUT_N;
    } else {
        cudaGetSymbolAddress((void**)&attn, g_attn_fallback);
    }

    cudaFuncSetAttribute(gemm_mma<0>, cudaFuncAttributeMaxDynamicSharedMemorySize, SMEM_DYN);
    cudaFuncSetAttribute(gemm_mma<2>, cudaFuncAttributeMaxDynamicSharedMemorySize, SMEM_DYN);

    // 1) fp32 -> split bf16 conversions
    {
        int n4 = (int)((size_t)Bb * Ss * Hh / 4);
        convert_split<<<n4 / 256, 256>>>((const float4*)enc, (uint2*)enc_hi, (uint2*)enc_lo, n4);
        convert_split<<<n4 / 256, 256>>>((const float4*)dec, (uint2*)dec_hi, (uint2*)dec_lo, n4);
        int w4 = (int)((size_t)Hh * 2 * Hh / 4);
        convert_split<<<w4 / 256, 256>>>((const float4*)W, (uint2*)W_hi, (uint2*)W_lo, w4);
    }

    // 2) approx logits = dec_hi . enc_hi^T   (single hh segment)
    {
        GemmArgs ga;
        ga.nseg = 1;
        long long sD = (long long)Tt * Hh, sE = (long long)Ss * Hh;
        ga.seg[0] = {dec_hi, enc_hi, Hh, Hh, Hh, sD, sE};
        gemm_mma<0><<<dim3(Ss / 128, Tt / 128, Bb), 128, SMEM_DYN>>>(
            ga, attn, nullptr, Ss, (long long)Tt * Ss);
    }

    // 3) refine candidate logits exactly (fp32) + softmax, in place
    refine_softmax<<<Bb * Tt, 256>>>(attn, enc, dec);

    // 4) ctx = P . enc as sparse gather, split-bf16 output
    sparse_ctx<<<Bb * Tt, 256>>>(attn, enc, ctx_hi, ctx_lo);

    // 5) out = tanh([ctx|dec] . W^T + b); cat split over 6 segments
    {
        GemmArgs ga;
        ga.nseg = 6;
        const int ldw = 2 * Hh;
        ga.seg[0] = {ctx_hi, W_hi,        Hh, Hh, ldw, 0, 0};
        ga.seg[1] = {dec_hi, W_hi + Hh,   Hh, Hh, ldw, 0, 0};
        ga.seg[2] = {ctx_lo, W_hi,        Hh, Hh, ldw, 0, 0};
        ga.seg[3] = {dec_lo, W_hi + Hh,   Hh, Hh, ldw, 0, 0};
        ga.seg[4] = {ctx_hi, W_lo,        Hh, Hh, ldw, 0, 0};
        ga.seg[5] = {dec_hi, W_lo + Hh,   Hh, Hh, ldw, 0, 0};
        gemm_mma<2><<<dim3(Hh / 128, (Bb * Tt) / 128, 1), 128, SMEM_DYN>>>(
            ga, outp, bias, Hh, 0);
    }
}

// round 14
// speedup vs baseline: 5.9704x; 1.6636x over previous
#include <cuda_runtime.h>
#include <cuda_fp16.h>
#include <math.h>
#include <stdint.h>

#define Bb 16
#define Tt 2048
#define Ss 2048
#define Hh 1024

typedef unsigned long long ull;

// ---------------------------------------------------------------------------
// Device-global scratch (no runtime allocation allowed) — fp16 single-term
// ---------------------------------------------------------------------------
__device__ __align__(256) __half g_enc_h[(size_t)Bb * Ss * Hh];
__device__ __align__(256) __half g_dec_h[(size_t)Bb * Tt * Hh];
__device__ __align__(256) __half g_ctx_h[(size_t)Bb * Tt * Hh];
__device__ __align__(256) __half g_W_h[(size_t)Hh * 2 * Hh];
__device__ __align__(16)  float g_attn_fallback[(size_t)Bb * Tt * Ss];

// ---------------------------------------------------------------------------
// PTX helpers (target-portable only: cp.async, ldmatrix, mma.sync)
// ---------------------------------------------------------------------------
__device__ __forceinline__ uint32_t cvta_s(const void* p) {
    uint32_t a;
    asm("{ .reg .u64 t; cvta.to.shared.u64 t, %1; cvt.u32.u64 %0, t; }"
        : "=r"(a) : "l"(p));
    return a;
}
__device__ __forceinline__ void cp16(uint32_t saddr, const void* gptr) {
    asm volatile("cp.async.cg.shared.global [%0], [%1], 16;"
                 :: "r"(saddr), "l"(__cvta_generic_to_global(gptr)));
}
__device__ __forceinline__ void cp_commit() {
    asm volatile("cp.async.commit_group;" ::: "memory");
}
template <int N>
__device__ __forceinline__ void cp_wait() {
    asm volatile("cp.async.wait_group %0;" :: "n"(N) : "memory");
}
__device__ __forceinline__ void ldsm4(uint32_t& r0, uint32_t& r1, uint32_t& r2,
                                      uint32_t& r3, uint32_t addr) {
    asm volatile("ldmatrix.sync.aligned.m8n8.x4.shared.b16 {%0,%1,%2,%3}, [%4];"
                 : "=r"(r0), "=r"(r1), "=r"(r2), "=r"(r3) : "r"(addr));
}
__device__ __forceinline__ void mma_f16(float* c, const uint32_t* a,
                                        uint32_t b0, uint32_t b1) {
    asm volatile(
        "mma.sync.aligned.m16n8k16.row.col.f32.f16.f16.f32 "
        "{%0,%1,%2,%3}, {%4,%5,%6,%7}, {%8,%9}, {%0,%1,%2,%3};"
        : "+f"(c[0]), "+f"(c[1]), "+f"(c[2]), "+f"(c[3])
        : "r"(a[0]), "r"(a[1]), "r"(a[2]), "r"(a[3]), "r"(b0), "r"(b1));
}
__device__ __forceinline__ uint32_t pkh(float x, float y) {
    __half2 t = __floats2half2_rn(x, y);
    return *reinterpret_cast<uint32_t*>(&t);
}

// ---------------------------------------------------------------------------
// Generic segmented fp16 MMA GEMM: D[m,n] = sum_seg A_s[m,:].B_s[n,:]
// CTA tile 128x128, 128 thr (4 warps 2x2, warp tile 64x64), K-chunks of 32,
// padded SMEM (stride 40 halves), 4-stage cp.async pipeline, ldmatrix+mma.sync.
// ---------------------------------------------------------------------------
struct Seg {
    const __half* A; const __half* B;
    int K; int lda; int ldb;
    long long sA; long long sB;
};
struct GemmArgs { Seg seg[2]; int nseg; };

#define KCH 32
#define SSTRIDE 80
#define ABUF 10240
#define NSTAGE 4
#define SMEM_DYN (2 * NSTAGE * ABUF)

__device__ __forceinline__ void load_chunk(uint32_t sA, uint32_t sB,
                                           const __half* A, const __half* Bm,
                                           int lda, int ldb, int tid) {
#pragma unroll
    for (int i = 0; i < 4; i++) {
        int lin = tid + (i << 7);
        int row = lin >> 2, seg = lin & 3;
        cp16(sA + row * SSTRIDE + seg * 16, A + (size_t)row * lda + seg * 8);
    }
#pragma unroll
    for (int i = 0; i < 4; i++) {
        int lin = tid + (i << 7);
        int row = lin >> 2, seg = lin & 3;
        cp16(sB + row * SSTRIDE + seg * 16, Bm + (size_t)row * ldb + seg * 8);
    }
}

// EPI: 0 = store fp32 C, 2 = tanh(v + bias) -> C
template <int EPI>
__global__ void __launch_bounds__(128, 2) gemm_mma(
    GemmArgs ga, float* __restrict__ C,
    const float* __restrict__ bias, int ldc, long long sC)
{
    extern __shared__ __align__(16) char smem[];
    const uint32_t sbase = cvta_s(smem);

    const int tid = threadIdx.x;
    const int lane = tid & 31;
    const int wid = tid >> 5;
    const int wm = (wid >> 1) * 64;
    const int wn = (wid & 1) * 64;
    const int z = blockIdx.z;
    const int m0 = blockIdx.y * 128;
    const int n0 = blockIdx.x * 128;

    float acc[4][8][4];
#pragma unroll
    for (int i = 0; i < 4; i++)
#pragma unroll
        for (int j = 0; j < 8; j++)
#pragma unroll
            for (int t = 0; t < 4; t++) acc[i][j][t] = 0.f;

    int total = 0;
#pragma unroll
    for (int i = 0; i < 2; i++)
        if (i < ga.nseg) total += ga.seg[i].K / KCH;

    const int lrow = lane & 15;
    const int lcol = (lane >> 4) * 16;

    int lsi = 0, lko = 0;
#pragma unroll
    for (int pf = 0; pf < NSTAGE - 1; pf++) {
        if (pf < total) {
            const Seg& sg = ga.seg[lsi];
            load_chunk(sbase + pf * ABUF, sbase + (NSTAGE + pf) * ABUF,
                       sg.A + z * sg.sA + (size_t)m0 * sg.lda + lko,
                       sg.B + z * sg.sB + (size_t)n0 * sg.ldb + lko,
                       sg.lda, sg.ldb, tid);
            cp_commit();
            lko += KCH;
            if (lko >= ga.seg[lsi].K) { lko = 0; lsi++; }
        }
    }

    for (int gc = 0; gc < total; gc++) {
        const int st = gc & (NSTAGE - 1);
        if (gc + 2 < total)      cp_wait<2>();
        else if (gc + 1 < total) cp_wait<1>();
        else                     cp_wait<0>();
        __syncthreads();

        if (gc + NSTAGE - 1 < total) {
            const int ls = (gc + NSTAGE - 1) & (NSTAGE - 1);
            const Seg& sg = ga.seg[lsi];
            load_chunk(sbase + ls * ABUF, sbase + (NSTAGE + ls) * ABUF,
                       sg.A + z * sg.sA + (size_t)m0 * sg.lda + lko,
                       sg.B + z * sg.sB + (size_t)n0 * sg.ldb + lko,
                       sg.lda, sg.ldb, tid);
            cp_commit();
            lko += KCH;
            if (lko >= ga.seg[lsi].K) { lko = 0; lsi++; }
        }

        const uint32_t aB = sbase + st * ABUF;
        const uint32_t bB = sbase + (NSTAGE + st) * ABUF;
#pragma unroll
        for (int ko = 0; ko < 2; ko++) {
            const uint32_t kb = ko * 32 + lcol;
            uint32_t af[4][4];
#pragma unroll
            for (int mi = 0; mi < 4; mi++) {
                uint32_t addr = aB + (uint32_t)(wm + mi * 16 + lrow) * SSTRIDE + kb;
                ldsm4(af[mi][0], af[mi][1], af[mi][2], af[mi][3], addr);
            }
            uint32_t bf_[4][4];
#pragma unroll
            for (int bi = 0; bi < 4; bi++) {
                uint32_t addr = bB + (uint32_t)(wn + bi * 16 + lrow) * SSTRIDE + kb;
                ldsm4(bf_[bi][0], bf_[bi][1], bf_[bi][2], bf_[bi][3], addr);
            }
#pragma unroll
            for (int mi = 0; mi < 4; mi++)
#pragma unroll
                for (int j = 0; j < 8; j++) {
                    const int bi = j >> 1, hi = j & 1;
                    mma_f16(acc[mi][j], af[mi], bf_[bi][hi], bf_[bi][hi + 2]);
                }
        }
    }

    const int rb = m0 + wm + (lane >> 2);
    const int cb = n0 + wn + (lane & 3) * 2;
#pragma unroll
    for (int mi = 0; mi < 4; mi++) {
#pragma unroll
        for (int j = 0; j < 8; j++) {
            const float* a4 = acc[mi][j];
            const int r0 = rb + mi * 16;
            const int col = cb + j * 8;
            if (EPI == 0) {
                float* p0 = C + (size_t)z * sC + (size_t)r0 * ldc + col;
                *(float2*)p0 = make_float2(a4[0], a4[1]);
                *(float2*)(p0 + 8 * (size_t)ldc) = make_float2(a4[2], a4[3]);
            } else {
                float2 bv = *(const float2*)(bias + col);
                float* p0 = C + (size_t)r0 * ldc + col;
                *(float2*)p0 = make_float2(tanhf(a4[0] + bv.x), tanhf(a4[1] + bv.y));
                *(float2*)(p0 + 8 * (size_t)ldc) =
                    make_float2(tanhf(a4[2] + bv.x), tanhf(a4[3] + bv.y));
            }
        }
    }
}

// ---------------------------------------------------------------------------
// fp32 -> fp16 convert, vectorized
// ---------------------------------------------------------------------------
__global__ void convert_h(const float4* __restrict__ in, uint2* __restrict__ out,
                          int n4)
{
    int i = blockIdx.x * blockDim.x + threadIdx.x;
    if (i >= n4) return;
    float4 v = in[i];
    out[i] = make_uint2(pkh(v.x, v.y), pkh(v.z, v.w));
}

// ---------------------------------------------------------------------------
// Refine + softmax: logits in attn are fp16-hh approximations (err sigma~0.013).
// Per row: approx max, compact candidates (logit > max-20), recompute those
// logits EXACTLY in fp32 (warp-per-candidate dot), patch, then softmax.
// ---------------------------------------------------------------------------
#define CAND_MAX 128
#define THRESH 20.0f

__global__ void __launch_bounds__(256) refine_softmax(
    float* __restrict__ attn, const float* __restrict__ enc,
    const float* __restrict__ dec)
{
    __shared__ float s_dec[Hh];
    __shared__ int   s_idx[CAND_MAX];
    __shared__ float s_exact[CAND_MAX];
    __shared__ int   s_cnt[256];
    __shared__ float red[8];

    const int row = blockIdx.x;
    const int b = row >> 11;
    const int t = row & 2047;
    const int tid = threadIdx.x;
    const int lane = tid & 31;
    const int wid = tid >> 5;
    float* p = attn + (size_t)row * Ss;

    {
        const float4 dv = *(const float4*)(dec + ((size_t)b * Tt + t) * Hh + tid * 4);
        *(float4*)&s_dec[tid * 4] = dv;
    }

    float pv[8];
    *(float4*)(pv)     = *(const float4*)(p + tid * 8);
    *(float4*)(pv + 4) = *(const float4*)(p + tid * 8 + 4);

    float m = pv[0];
#pragma unroll
    for (int i = 1; i < 8; i++) m = fmaxf(m, pv[i]);
#pragma unroll
    for (int o = 16; o > 0; o >>= 1) m = fmaxf(m, __shfl_xor_sync(0xffffffffu, m, o));
    if (lane == 0) red[wid] = m;
    __syncthreads();
    float mm = red[0];
#pragma unroll
    for (int i = 1; i < 8; i++) mm = fmaxf(mm, red[i]);

    const float thr = mm - THRESH;
    int cnt = 0;
#pragma unroll
    for (int i = 0; i < 8; i++) cnt += (pv[i] > thr) ? 1 : 0;
    s_cnt[tid] = cnt;
    __syncthreads();
    for (int off = 1; off < 256; off <<= 1) {
        int v = s_cnt[tid];
        int add = (tid >= off) ? s_cnt[tid - off] : 0;
        __syncthreads();
        s_cnt[tid] = v + add;
        __syncthreads();
    }
    const int total0 = s_cnt[255];
    const int total = (total0 < CAND_MAX) ? total0 : CAND_MAX;
    {
        int wr = s_cnt[tid] - cnt;
#pragma unroll
        for (int i = 0; i < 8; i++) {
            if (pv[i] > thr) {
                if (wr < CAND_MAX) s_idx[wr] = tid * 8 + i;
                wr++;
            }
        }
    }
    __syncthreads();

    for (int c = wid; c < total; c += 8) {
        const float* er = enc + ((size_t)b * Ss + s_idx[c]) * Hh;
        float sum = 0.f;
#pragma unroll
        for (int k = 0; k < 8; k++) {
            const int e0 = (lane + k * 32) * 4;
            const float4 e = *(const float4*)(er + e0);
            const float4 d = *(const float4*)&s_dec[e0];
            sum += e.x * d.x + e.y * d.y + e.z * d.z + e.w * d.w;
        }
#pragma unroll
        for (int o = 16; o > 0; o >>= 1) sum += __shfl_xor_sync(0xffffffffu, sum, o);
        if (lane == 0) s_exact[c] = sum;
    }
    __syncthreads();

    {
        int wr = s_cnt[tid] - cnt;
#pragma unroll
        for (int i = 0; i < 8; i++) {
            if (pv[i] > thr) {
                if (wr < total) pv[i] = s_exact[wr];
                wr++;
            }
        }
    }
    __syncthreads();

    float m2 = pv[0];
#pragma unroll
    for (int i = 1; i < 8; i++) m2 = fmaxf(m2, pv[i]);
#pragma unroll
    for (int o = 16; o > 0; o >>= 1) m2 = fmaxf(m2, __shfl_xor_sync(0xffffffffu, m2, o));
    if (lane == 0) red[wid] = m2;
    __syncthreads();
    float mx = red[0];
#pragma unroll
    for (int i = 1; i < 8; i++) mx = fmaxf(mx, red[i]);
    __syncthreads();

    float s = 0.f;
#pragma unroll
    for (int i = 0; i < 8; i++) { pv[i] = __expf(pv[i] - mx); s += pv[i]; }
#pragma unroll
    for (int o = 16; o > 0; o >>= 1) s += __shfl_xor_sync(0xffffffffu, s, o);
    if (lane == 0) red[wid] = s;
    __syncthreads();
    float ss = 0.f;
#pragma unroll
    for (int i = 0; i < 8; i++) ss += red[i];
    const float inv = 1.0f / ss;

#pragma unroll
    for (int i = 0; i < 8; i++) pv[i] *= inv;
    *(float4*)(p + tid * 8)     = *(float4*)(pv);
    *(float4*)(p + tid * 8 + 4) = *(float4*)(pv + 4);
}

// ---------------------------------------------------------------------------
// Sparse ctx: ctx[row,:] = sum_{s: p[row,s] > TAU} p[row,s] * enc[b,s,:]
// fp32 accumulate, fp16 store.
// ---------------------------------------------------------------------------
#define TAU 1e-7f
__global__ void __launch_bounds__(256) sparse_ctx(
    const float* __restrict__ attn, const float* __restrict__ enc,
    __half* __restrict__ Ch)
{
    __shared__ int   s_idx[Ss];
    __shared__ float s_p[Ss];
    __shared__ int   s_cnt[256];

    const int row = blockIdx.x;
    const int b = row >> 11;
    const int tid = threadIdx.x;
    const float* p = attn + (size_t)row * Ss;

    float pv[8];
    *(float4*)(pv)     = *(const float4*)(p + tid * 8);
    *(float4*)(pv + 4) = *(const float4*)(p + tid * 8 + 4);
    int cnt = 0;
#pragma unroll
    for (int i = 0; i < 8; i++) cnt += (pv[i] > TAU) ? 1 : 0;

    s_cnt[tid] = cnt;
    __syncthreads();
    for (int off = 1; off < 256; off <<= 1) {
        int v = s_cnt[tid];
        int add = (tid >= off) ? s_cnt[tid - off] : 0;
        __syncthreads();
        s_cnt[tid] = v + add;
        __syncthreads();
    }
    int wr = s_cnt[tid] - cnt;
    const int total = s_cnt[255];
#pragma unroll
    for (int i = 0; i < 8; i++) {
        if (pv[i] > TAU) { s_idx[wr] = tid * 8 + i; s_p[wr] = pv[i]; wr++; }
    }
    __syncthreads();

    float4 acc = make_float4(0.f, 0.f, 0.f, 0.f);
    const float* eb = enc + (size_t)b * Ss * Hh;
    for (int i = 0; i < total; i++) {
        const float w = s_p[i];
        const float4 e = *(const float4*)(eb + (size_t)s_idx[i] * Hh + tid * 4);
        acc.x += w * e.x; acc.y += w * e.y; acc.z += w * e.z; acc.w += w * e.w;
    }

    const size_t off = (size_t)row * Hh + tid * 4;
    *(uint2*)(Ch + off) = make_uint2(pkh(acc.x, acc.y), pkh(acc.z, acc.w));
}

// ---------------------------------------------------------------------------
// Launch
// ---------------------------------------------------------------------------
extern "C" void kernel_launch(void* const* d_in, const int* in_sizes, int n_in,
                              void* d_out, int out_size)
{
    const float* enc  = (const float*)d_in[0];
    const float* dec  = (const float*)d_in[1];
    const float* W    = (const float*)d_in[2];
    const float* bias = (const float*)d_in[3];
    float* outp = (float*)d_out;

    const size_t OUT_N = (size_t)Bb * Tt * Hh;
    const size_t ATT_N = (size_t)Bb * Tt * Ss;

    __half *enc_h, *dec_h, *ctx_h, *W_h;
    cudaGetSymbolAddress((void**)&enc_h, g_enc_h);
    cudaGetSymbolAddress((void**)&dec_h, g_dec_h);
    cudaGetSymbolAddress((void**)&ctx_h, g_ctx_h);
    cudaGetSymbolAddress((void**)&W_h, g_W_h);

    float* attn;
    if ((size_t)out_size >= OUT_N + ATT_N) {
        attn = outp + OUT_N;
    } else {
        cudaGetSymbolAddress((void**)&attn, g_attn_fallback);
    }

    cudaFuncSetAttribute(gemm_mma<0>, cudaFuncAttributeMaxDynamicSharedMemorySize, SMEM_DYN);
    cudaFuncSetAttribute(gemm_mma<2>, cudaFuncAttributeMaxDynamicSharedMemorySize, SMEM_DYN);

    // 1) fp32 -> fp16 conversions
    {
        int n4 = (int)((size_t)Bb * Ss * Hh / 4);
        convert_h<<<n4 / 256, 256>>>((const float4*)enc, (uint2*)enc_h, n4);
        convert_h<<<n4 / 256, 256>>>((const float4*)dec, (uint2*)dec_h, n4);
        int w4 = (int)((size_t)Hh * 2 * Hh / 4);
        convert_h<<<w4 / 256, 256>>>((const float4*)W, (uint2*)W_h, w4);
    }

    // 2) approx logits = dec_h . enc_h^T (fp16 hh, err sigma ~0.013)
    {
        GemmArgs ga;
        ga.nseg = 1;
        long long sD = (long long)Tt * Hh, sE = (long long)Ss * Hh;
        ga.seg[0] = {dec_h, enc_h, Hh, Hh, Hh, sD, sE};
        gemm_mma<0><<<dim3(Ss / 128, Tt / 128, Bb), 128, SMEM_DYN>>>(
            ga, attn, nullptr, Ss, (long long)Tt * Ss);
    }

    // 3) refine candidate logits exactly (fp32) + softmax, in place
    refine_softmax<<<Bb * Tt, 256>>>(attn, enc, dec);

    // 4) ctx = P . enc as sparse gather, fp16 output
    sparse_ctx<<<Bb * Tt, 256>>>(attn, enc, ctx_h);

    // 5) out = tanh([ctx|dec] . W^T + b); fp16 hh, 2 segments
    {
        GemmArgs ga;
        ga.nseg = 2;
        const int ldw = 2 * Hh;
        ga.seg[0] = {ctx_h, W_h,      Hh, Hh, ldw, 0, 0};
        ga.seg[1] = {dec_h, W_h + Hh, Hh, Hh, ldw, 0, 0};
        gemm_mma<2><<<dim3(Hh / 128, (Bb * Tt) / 128, 1), 128, SMEM_DYN>>>(
            ga, outp, bias, Hh, 0);
    }
}

// round 17
// speedup vs baseline: 6.1485x; 1.0298x over previous
#include <cuda_runtime.h>
#include <cuda_fp16.h>
#include <math.h>
#include <stdint.h>

#define Bb 16
#define Tt 2048
#define Ss 2048
#define Hh 1024

typedef unsigned long long ull;

// ---------------------------------------------------------------------------
// Device-global scratch (no runtime allocation allowed)
// ---------------------------------------------------------------------------
__device__ __align__(256) uint8_t g_enc_f8[(size_t)Bb * Ss * Hh];
__device__ __align__(256) uint8_t g_dec_f8[(size_t)Bb * Tt * Hh];
__device__ __align__(256) __half  g_dec_h[(size_t)Bb * Tt * Hh];
__device__ __align__(256) __half  g_ctx_h[(size_t)Bb * Tt * Hh];
__device__ __align__(256) __half  g_W_h[(size_t)Hh * 2 * Hh];
__device__ __align__(16)  float   g_attn_fallback[(size_t)Bb * Tt * Ss];

// ---------------------------------------------------------------------------
// PTX helpers (target-portable: cp.async, ldmatrix, mma.sync f16 + e4m3)
// ---------------------------------------------------------------------------
__device__ __forceinline__ uint32_t cvta_s(const void* p) {
    uint32_t a;
    asm("{ .reg .u64 t; cvta.to.shared.u64 t, %1; cvt.u32.u64 %0, t; }"
        : "=r"(a) : "l"(p));
    return a;
}
__device__ __forceinline__ void cp16(uint32_t saddr, const void* gptr) {
    asm volatile("cp.async.cg.shared.global [%0], [%1], 16;"
                 :: "r"(saddr), "l"(__cvta_generic_to_global(gptr)));
}
__device__ __forceinline__ void cp_commit() {
    asm volatile("cp.async.commit_group;" ::: "memory");
}
template <int N>
__device__ __forceinline__ void cp_wait() {
    asm volatile("cp.async.wait_group %0;" :: "n"(N) : "memory");
}
__device__ __forceinline__ void ldsm4(uint32_t& r0, uint32_t& r1, uint32_t& r2,
                                      uint32_t& r3, uint32_t addr) {
    asm volatile("ldmatrix.sync.aligned.m8n8.x4.shared.b16 {%0,%1,%2,%3}, [%4];"
                 : "=r"(r0), "=r"(r1), "=r"(r2), "=r"(r3) : "r"(addr));
}
__device__ __forceinline__ void mma_f16(float* c, const uint32_t* a,
                                        uint32_t b0, uint32_t b1) {
    asm volatile(
        "mma.sync.aligned.m16n8k16.row.col.f32.f16.f16.f32 "
        "{%0,%1,%2,%3}, {%4,%5,%6,%7}, {%8,%9}, {%0,%1,%2,%3};"
        : "+f"(c[0]), "+f"(c[1]), "+f"(c[2]), "+f"(c[3])
        : "r"(a[0]), "r"(a[1]), "r"(a[2]), "r"(a[3]), "r"(b0), "r"(b1));
}
__device__ __forceinline__ void mma_e4m3(float* c, const uint32_t* a,
                                         uint32_t b0, uint32_t b1) {
    asm volatile(
        "mma.sync.aligned.m16n8k32.row.col.f32.e4m3.e4m3.f32 "
        "{%0,%1,%2,%3}, {%4,%5,%6,%7}, {%8,%9}, {%0,%1,%2,%3};"
        : "+f"(c[0]), "+f"(c[1]), "+f"(c[2]), "+f"(c[3])
        : "r"(a[0]), "r"(a[1]), "r"(a[2]), "r"(a[3]), "r"(b0), "r"(b1));
}
__device__ __forceinline__ uint32_t pkh(float x, float y) {
    __half2 t = __floats2half2_rn(x, y);
    return *reinterpret_cast<uint32_t*>(&t);
}
__device__ __forceinline__ uint32_t pk4_e4m3(float4 v) {
    uint16_t lo, hi;
    asm("cvt.rn.satfinite.e4m3x2.f32 %0, %1, %2;" : "=h"(lo) : "f"(v.y), "f"(v.x));
    asm("cvt.rn.satfinite.e4m3x2.f32 %0, %1, %2;" : "=h"(hi) : "f"(v.w), "f"(v.z));
    return (uint32_t)lo | ((uint32_t)hi << 16);
}

// ---------------------------------------------------------------------------
// Generic segmented MMA GEMM, byte-based K addressing.
// F8=0: fp16 elements (k16/step); F8=1: e4m3 (k32/step). Each 64-byte K-chunk
// = two ldsm+mma steps either way — identical SMEM geometry and control flow.
// CTA tile 128x128, 128 thr (4 warps 2x2, warp tile 64x64), 4-stage cp.async.
// ---------------------------------------------------------------------------
struct Seg {
    const char* A; const char* B;
    int Kb;            // K extent in BYTES
    int lda_b; int ldb_b;
    long long sA_b; long long sB_b;
};
struct GemmArgs { Seg seg[2]; int nseg; };

#define SSTRIDE 80
#define ABUF 10240
#define NSTAGE 4
#define SMEM_DYN (2 * NSTAGE * ABUF)

__device__ __forceinline__ void load_chunk(uint32_t sA, uint32_t sB,
                                           const char* A, const char* Bm,
                                           int lda_b, int ldb_b, int tid) {
#pragma unroll
    for (int i = 0; i < 4; i++) {
        int lin = tid + (i << 7);
        int row = lin >> 2, seg = lin & 3;
        cp16(sA + row * SSTRIDE + seg * 16, A + (size_t)row * lda_b + seg * 16);
    }
#pragma unroll
    for (int i = 0; i < 4; i++) {
        int lin = tid + (i << 7);
        int row = lin >> 2, seg = lin & 3;
        cp16(sB + row * SSTRIDE + seg * 16, Bm + (size_t)row * ldb_b + seg * 16);
    }
}

// EPI: 0 = store fp32 C, 2 = tanh(v + bias) -> C
template <int EPI, int F8>
__global__ void __launch_bounds__(128, 2) gemm_mma(
    GemmArgs ga, float* __restrict__ C,
    const float* __restrict__ bias, int ldc, long long sC)
{
    extern __shared__ __align__(16) char smem[];
    const uint32_t sbase = cvta_s(smem);

    const int tid = threadIdx.x;
    const int lane = tid & 31;
    const int wid = tid >> 5;
    const int wm = (wid >> 1) * 64;
    const int wn = (wid & 1) * 64;
    const int z = blockIdx.z;
    const int m0 = blockIdx.y * 128;
    const int n0 = blockIdx.x * 128;

    float acc[4][8][4];
#pragma unroll
    for (int i = 0; i < 4; i++)
#pragma unroll
        for (int j = 0; j < 8; j++)
#pragma unroll
            for (int t = 0; t < 4; t++) acc[i][j][t] = 0.f;

    int total = 0;
#pragma unroll
    for (int i = 0; i < 2; i++)
        if (i < ga.nseg) total += ga.seg[i].Kb >> 6;

    const int lrow = lane & 15;
    const int lcol = (lane >> 4) * 16;

    int lsi = 0, lko = 0;   // lko in bytes
#pragma unroll
    for (int pf = 0; pf < NSTAGE - 1; pf++) {
        if (pf < total) {
            const Seg& sg = ga.seg[lsi];
            load_chunk(sbase + pf * ABUF, sbase + (NSTAGE + pf) * ABUF,
                       sg.A + z * sg.sA_b + (size_t)m0 * sg.lda_b + lko,
                       sg.B + z * sg.sB_b + (size_t)n0 * sg.ldb_b + lko,
                       sg.lda_b, sg.ldb_b, tid);
            cp_commit();
            lko += 64;
            if (lko >= ga.seg[lsi].Kb) { lko = 0; lsi++; }
        }
    }

    for (int gc = 0; gc < total; gc++) {
        const int st = gc & (NSTAGE - 1);
        if (gc + 2 < total)      cp_wait<2>();
        else if (gc + 1 < total) cp_wait<1>();
        else                     cp_wait<0>();
        __syncthreads();

        if (gc + NSTAGE - 1 < total) {
            const int ls = (gc + NSTAGE - 1) & (NSTAGE - 1);
            const Seg& sg = ga.seg[lsi];
            load_chunk(sbase + ls * ABUF, sbase + (NSTAGE + ls) * ABUF,
                       sg.A + z * sg.sA_b + (size_t)m0 * sg.lda_b + lko,
                       sg.B + z * sg.sB_b + (size_t)n0 * sg.ldb_b + lko,
                       sg.lda_b, sg.ldb_b, tid);
            cp_commit();
            lko += 64;
            if (lko >= ga.seg[lsi].Kb) { lko = 0; lsi++; }
        }

        const uint32_t aB = sbase + st * ABUF;
        const uint32_t bB = sbase + (NSTAGE + st) * ABUF;
#pragma unroll
        for (int ko = 0; ko < 2; ko++) {       // two 32-byte steps (k16 f16 / k32 fp8)
            const uint32_t kb = ko * 32 + lcol;
            uint32_t af[4][4];
#pragma unroll
            for (int mi = 0; mi < 4; mi++) {
                uint32_t addr = aB + (uint32_t)(wm + mi * 16 + lrow) * SSTRIDE + kb;
                ldsm4(af[mi][0], af[mi][1], af[mi][2], af[mi][3], addr);
            }
            uint32_t bf_[4][4];
#pragma unroll
            for (int bi = 0; bi < 4; bi++) {
                uint32_t addr = bB + (uint32_t)(wn + bi * 16 + lrow) * SSTRIDE + kb;
                ldsm4(bf_[bi][0], bf_[bi][1], bf_[bi][2], bf_[bi][3], addr);
            }
#pragma unroll
            for (int mi = 0; mi < 4; mi++)
#pragma unroll
                for (int j = 0; j < 8; j++) {
                    const int bi = j >> 1, hi = j & 1;
                    if (F8)
                        mma_e4m3(acc[mi][j], af[mi], bf_[bi][hi], bf_[bi][hi + 2]);
                    else
                        mma_f16(acc[mi][j], af[mi], bf_[bi][hi], bf_[bi][hi + 2]);
                }
        }
    }

    const int rb = m0 + wm + (lane >> 2);
    const int cb = n0 + wn + (lane & 3) * 2;
#pragma unroll
    for (int mi = 0; mi < 4; mi++) {
#pragma unroll
        for (int j = 0; j < 8; j++) {
            const float* a4 = acc[mi][j];
            const int r0 = rb + mi * 16;
            const int col = cb + j * 8;
            if (EPI == 0) {
                float* p0 = C + (size_t)z * sC + (size_t)r0 * ldc + col;
                *(float2*)p0 = make_float2(a4[0], a4[1]);
                *(float2*)(p0 + 8 * (size_t)ldc) = make_float2(a4[2], a4[3]);
            } else {
                float2 bv = *(const float2*)(bias + col);
                float* p0 = C + (size_t)r0 * ldc + col;
                *(float2*)p0 = make_float2(tanhf(a4[0] + bv.x), tanhf(a4[1] + bv.y));
                *(float2*)(p0 + 8 * (size_t)ldc) =
                    make_float2(tanhf(a4[2] + bv.x), tanhf(a4[3] + bv.y));
            }
        }
    }
}

// ---------------------------------------------------------------------------
// Converters
// ---------------------------------------------------------------------------
__global__ void convert_f8(const float4* __restrict__ in, uint2* __restrict__ o8,
                           int n8)
{
    int i = blockIdx.x * blockDim.x + threadIdx.x;
    if (i >= n8) return;
    float4 a = in[2 * i], b = in[2 * i + 1];
    o8[i] = make_uint2(pk4_e4m3(a), pk4_e4m3(b));
}
__global__ void convert_both(const float4* __restrict__ in, uint2* __restrict__ oh,
                             uint2* __restrict__ o8, int n8)
{
    int i = blockIdx.x * blockDim.x + threadIdx.x;
    if (i >= n8) return;
    float4 a = in[2 * i], b = in[2 * i + 1];
    oh[2 * i]     = make_uint2(pkh(a.x, a.y), pkh(a.z, a.w));
    oh[2 * i + 1] = make_uint2(pkh(b.x, b.y), pkh(b.z, b.w));
    o8[i] = make_uint2(pk4_e4m3(a), pk4_e4m3(b));
}
__global__ void convert_h(const float4* __restrict__ in, uint2* __restrict__ out,
                          int n4)
{
    int i = blockIdx.x * blockDim.x + threadIdx.x;
    if (i >= n4) return;
    float4 v = in[i];
    out[i] = make_uint2(pkh(v.x, v.y), pkh(v.z, v.w));
}

// ---------------------------------------------------------------------------
// Fused refine + softmax + sparse ctx.
// Logits in attn are fp8-approx (err sigma ~1.6). Per row: approx max, compact
// candidates (logit > max-26), recompute them EXACTLY in fp32, patch, softmax,
// then ctx[row,:] = sum_{p>TAU} p * enc[b,s,:] using in-register attn values.
// ---------------------------------------------------------------------------
#define CAND_MAX 128
#define THRESH 26.0f
#define TAU 1e-7f

__global__ void __launch_bounds__(256) refine_softmax_ctx(
    float* __restrict__ attn, const float* __restrict__ enc,
    const float* __restrict__ dec, __half* __restrict__ Ch)
{
    __shared__ float s_dec[Hh];
    __shared__ int   s_idx[CAND_MAX];
    __shared__ float s_exact[CAND_MAX];
    __shared__ int   s_cnt[256];
    __shared__ float red[8];
    __shared__ int   s_gi[Ss / 4];     // survivor indices (cap: worst-case safe-guarded)
    __shared__ float s_gp[Ss / 4];

    const int row = blockIdx.x;
    const int b = row >> 11;
    const int t = row & 2047;
    const int tid = threadIdx.x;
    const int lane = tid & 31;
    const int wid = tid >> 5;
    float* p = attn + (size_t)row * Ss;

    {
        const float4 dv = *(const float4*)(dec + ((size_t)b * Tt + t) * Hh + tid * 4);
        *(float4*)&s_dec[tid * 4] = dv;
    }

    float pv[8];
    *(float4*)(pv)     = *(const float4*)(p + tid * 8);
    *(float4*)(pv + 4) = *(const float4*)(p + tid * 8 + 4);

    // approx row max
    float m = pv[0];
#pragma unroll
    for (int i = 1; i < 8; i++) m = fmaxf(m, pv[i]);
#pragma unroll
    for (int o = 16; o > 0; o >>= 1) m = fmaxf(m, __shfl_xor_sync(0xffffffffu, m, o));
    if (lane == 0) red[wid] = m;
    __syncthreads();
    float mm = red[0];
#pragma unroll
    for (int i = 1; i < 8; i++) mm = fmaxf(mm, red[i]);

    // candidate compaction (order-preserving)
    const float thr = mm - THRESH;
    int cnt = 0;
#pragma unroll
    for (int i = 0; i < 8; i++) cnt += (pv[i] > thr) ? 1 : 0;
    s_cnt[tid] = cnt;
    __syncthreads();
    for (int off = 1; off < 256; off <<= 1) {
        int v = s_cnt[tid];
        int add = (tid >= off) ? s_cnt[tid - off] : 0;
        __syncthreads();
        s_cnt[tid] = v + add;
        __syncthreads();
    }
    const int total0 = s_cnt[255];
    const int total = (total0 < CAND_MAX) ? total0 : CAND_MAX;
    {
        int wr = s_cnt[tid] - cnt;
#pragma unroll
        for (int i = 0; i < 8; i++) {
            if (pv[i] > thr) {
                if (wr < CAND_MAX) s_idx[wr] = tid * 8 + i;
                wr++;
            }
        }
    }
    __syncthreads();

    // exact fp32 dots: one warp per candidate
    for (int c = wid; c < total; c += 8) {
        const float* er = enc + ((size_t)b * Ss + s_idx[c]) * Hh;
        float sum = 0.f;
#pragma unroll
        for (int k = 0; k < 8; k++) {
            const int e0 = (lane + k * 32) * 4;
            const float4 e = *(const float4*)(er + e0);
            const float4 d = *(const float4*)&s_dec[e0];
            sum += e.x * d.x + e.y * d.y + e.z * d.z + e.w * d.w;
        }
#pragma unroll
        for (int o = 16; o > 0; o >>= 1) sum += __shfl_xor_sync(0xffffffffu, sum, o);
        if (lane == 0) s_exact[c] = sum;
    }
    __syncthreads();

    // patch local copies with exact logits
    {
        int wr = s_cnt[tid] - cnt;
#pragma unroll
        for (int i = 0; i < 8; i++) {
            if (pv[i] > thr) {
                if (wr < total) pv[i] = s_exact[wr];
                wr++;
            }
        }
    }
    __syncthreads();

    // exact max over patched values
    float m2 = pv[0];
#pragma unroll
    for (int i = 1; i < 8; i++) m2 = fmaxf(m2, pv[i]);
#pragma unroll
    for (int o = 16; o > 0; o >>= 1) m2 = fmaxf(m2, __shfl_xor_sync(0xffffffffu, m2, o));
    if (lane == 0) red[wid] = m2;
    __syncthreads();
    float mx = red[0];
#pragma unroll
    for (int i = 1; i < 8; i++) mx = fmaxf(mx, red[i]);
    __syncthreads();

    // exp + sum
    float s = 0.f;
#pragma unroll
    for (int i = 0; i < 8; i++) { pv[i] = __expf(pv[i] - mx); s += pv[i]; }
#pragma unroll
    for (int o = 16; o > 0; o >>= 1) s += __shfl_xor_sync(0xffffffffu, s, o);
    if (lane == 0) red[wid] = s;
    __syncthreads();
    float ss = 0.f;
#pragma unroll
    for (int i = 0; i < 8; i++) ss += red[i];
    const float inv = 1.0f / ss;

#pragma unroll
    for (int i = 0; i < 8; i++) pv[i] *= inv;
    *(float4*)(p + tid * 8)     = *(float4*)(pv);
    *(float4*)(p + tid * 8 + 4) = *(float4*)(pv + 4);

    // ---- fused sparse ctx: compact survivors p > TAU (deterministic scan) ----
    __syncthreads();
    int cnt2 = 0;
#pragma unroll
    for (int i = 0; i < 8; i++) cnt2 += (pv[i] > TAU) ? 1 : 0;
    s_cnt[tid] = cnt2;
    __syncthreads();
    for (int off = 1; off < 256; off <<= 1) {
        int v = s_cnt[tid];
        int add = (tid >= off) ? s_cnt[tid - off] : 0;
        __syncthreads();
        s_cnt[tid] = v + add;
        __syncthreads();
    }
    {
        int wr = s_cnt[tid] - cnt2;
#pragma unroll
        for (int i = 0; i < 8; i++) {
            if (pv[i] > TAU) {
                if (wr < Ss / 4) { s_gi[wr] = tid * 8 + i; s_gp[wr] = pv[i]; }
                wr++;
            }
        }
    }
    const int nsurv0 = s_cnt[255];
    const int nsurv = (nsurv0 < Ss / 4) ? nsurv0 : (Ss / 4);
    __syncthreads();

    float4 acc = make_float4(0.f, 0.f, 0.f, 0.f);
    const float* eb = enc + (size_t)b * Ss * Hh;
    for (int i = 0; i < nsurv; i++) {
        const float w = s_gp[i];
        const float4 e = *(const float4*)(eb + (size_t)s_gi[i] * Hh + tid * 4);
        acc.x += w * e.x; acc.y += w * e.y; acc.z += w * e.z; acc.w += w * e.w;
    }
    const size_t off = (size_t)row * Hh + tid * 4;
    *(uint2*)(Ch + off) = make_uint2(pkh(acc.x, acc.y), pkh(acc.z, acc.w));
}

// ---------------------------------------------------------------------------
// Launch
// ---------------------------------------------------------------------------
extern "C" void kernel_launch(void* const* d_in, const int* in_sizes, int n_in,
                              void* d_out, int out_size)
{
    const float* enc  = (const float*)d_in[0];
    const float* dec  = (const float*)d_in[1];
    const float* W    = (const float*)d_in[2];
    const float* bias = (const float*)d_in[3];
    float* outp = (float*)d_out;

    const size_t OUT_N = (size_t)Bb * Tt * Hh;
    const size_t ATT_N = (size_t)Bb * Tt * Ss;

    uint8_t *enc_f8, *dec_f8;
    __half *dec_h, *ctx_h, *W_h;
    cudaGetSymbolAddress((void**)&enc_f8, g_enc_f8);
    cudaGetSymbolAddress((void**)&dec_f8, g_dec_f8);
    cudaGetSymbolAddress((void**)&dec_h, g_dec_h);
    cudaGetSymbolAddress((void**)&ctx_h, g_ctx_h);
    cudaGetSymbolAddress((void**)&W_h, g_W_h);

    float* attn;
    if ((size_t)out_size >= OUT_N + ATT_N) {
        attn = outp + OUT_N;
    } else {
        cudaGetSymbolAddress((void**)&attn, g_attn_fallback);
    }

    cudaFuncSetAttribute((const void*)gemm_mma<0, 1>,
                         cudaFuncAttributeMaxDynamicSharedMemorySize, SMEM_DYN);
    cudaFuncSetAttribute((const void*)gemm_mma<2, 0>,
                         cudaFuncAttributeMaxDynamicSharedMemorySize, SMEM_DYN);

    // 1) conversions: enc -> fp8; dec -> fp8 + fp16; W -> fp16
    {
        int n8 = (int)((size_t)Bb * Ss * Hh / 8);
        convert_f8<<<(n8 + 255) / 256, 256>>>((const float4*)enc, (uint2*)enc_f8, n8);
        convert_both<<<(n8 + 255) / 256, 256>>>((const float4*)dec, (uint2*)dec_h,
                                                (uint2*)dec_f8, n8);
        int w4 = (int)((size_t)Hh * 2 * Hh / 4);
        convert_h<<<w4 / 256, 256>>>((const float4*)W, (uint2*)W_h, w4);
    }

    // 2) approx logits = dec_f8 . enc_f8^T  (e4m3 k32 MMA, half the instructions)
    {
        GemmArgs ga;
        ga.nseg = 1;
        ga.seg[0] = {(const char*)dec_f8, (const char*)enc_f8, Hh, Hh, Hh,
                     (long long)Tt * Hh, (long long)Ss * Hh};
        gemm_mma<0, 1><<<dim3(Ss / 128, Tt / 128, Bb), 128, SMEM_DYN>>>(
            ga, attn, nullptr, Ss, (long long)Tt * Ss);
    }

    // 3) fused: refine candidates exactly + softmax + sparse ctx (fp16 out)
    refine_softmax_ctx<<<Bb * Tt, 256>>>(attn, enc, dec, ctx_h);

    // 4) out = tanh([ctx|dec] . W^T + b); fp16, 2 segments
    {
        GemmArgs ga;
        ga.nseg = 2;
        const int ldw_b = 2 * Hh * 2;
        ga.seg[0] = {(const char*)ctx_h, (const char*)W_h, Hh * 2, Hh * 2, ldw_b, 0, 0};
        ga.seg[1] = {(const char*)dec_h, (const char*)(W_h + Hh), Hh * 2, Hh * 2, ldw_b, 0, 0};
        gemm_mma<2, 0><<<dim3(Hh / 128, (Bb * Tt) / 128, 1), 128, SMEM_DYN>>>(
            ga, outp, bias, Hh, 0);
    }
}